// round 15
// baseline (speedup 1.0000x reference)
#include <cuda_runtime.h>
#include <cuda_bf16.h>
#include <stdint.h>
#include <math.h>

#define Nn 2048
#define Dd 256
#define Hh 8
#define DKk 32
#define Ll 4
#define DFFf 1024
#define NEDGEe 5

typedef __nv_bfloat16 bf16;

// ---------------- portable MMA helpers (validated R8-R14) ----------------
__device__ __forceinline__ uint32_t smem_u32(const void* p) {
    uint32_t a;
    asm("{ .reg .u64 t; cvta.to.shared.u64 t, %1; cvt.u32.u64 %0, t; }" : "=r"(a) : "l"(p));
    return a;
}
__device__ __forceinline__ void ldsm4(uint32_t& r0, uint32_t& r1, uint32_t& r2, uint32_t& r3,
                                      uint32_t addr) {
    asm volatile("ldmatrix.sync.aligned.m8n8.x4.shared.b16 {%0,%1,%2,%3}, [%4];"
                 : "=r"(r0), "=r"(r1), "=r"(r2), "=r"(r3)
                 : "r"(addr));
}
__device__ __forceinline__ void ldsm4t(uint32_t& r0, uint32_t& r1, uint32_t& r2, uint32_t& r3,
                                       uint32_t addr) {
    asm volatile("ldmatrix.sync.aligned.m8n8.x4.trans.shared.b16 {%0,%1,%2,%3}, [%4];"
                 : "=r"(r0), "=r"(r1), "=r"(r2), "=r"(r3)
                 : "r"(addr));
}
__device__ __forceinline__ void mma_bf16(float* d, const uint32_t* a, const uint32_t* b) {
    asm volatile(
        "mma.sync.aligned.m16n8k16.row.col.f32.bf16.bf16.f32 "
        "{%0,%1,%2,%3}, {%4,%5,%6,%7}, {%8,%9}, {%0,%1,%2,%3};"
        : "+f"(d[0]), "+f"(d[1]), "+f"(d[2]), "+f"(d[3])
        : "r"(a[0]), "r"(a[1]), "r"(a[2]), "r"(a[3]), "r"(b[0]), "r"(b[1]));
}
__device__ __forceinline__ uint32_t pack2bf(float a, float b) {
    uint32_t r;
    asm("cvt.rn.bf16x2.f32 %0, %1, %2;" : "=r"(r) : "f"(b), "f"(a));
    return r;
}
__device__ __forceinline__ float ex2f(float x) {
    float y;
    asm("ex2.approx.f32 %0, %1;" : "=f"(y) : "f"(x));
    return y;
}
__device__ __forceinline__ void cpa16(uint32_t dst, const void* src) {
    asm volatile("cp.async.cg.shared.global [%0], [%1], 16;" :: "r"(dst), "l"(src));
}
#define CP_COMMIT() asm volatile("cp.async.commit_group;" ::: "memory")
#define CP_WAIT(n) asm volatile("cp.async.wait_group %0;" :: "n"(n) : "memory")
#define GBAR(id) asm volatile("bar.sync %0, %1;" :: "r"(id), "r"(128) : "memory")

// ---------------- scratch ----------------
__device__ float g_x[Nn * Dd];
__device__ float g_part[2 * Nn * Dd];
__device__ unsigned char g_e8[Nn * Nn];
__device__ float g_pool[2 * Dd];
__device__ bf16 g_xh[Nn * Dd], g_xl[Nn * Dd];
__device__ bf16 g_qh[Nn * Dd], g_ql[Nn * Dd];
__device__ bf16 g_kh[Nn * Dd], g_kl[Nn * Dd];
__device__ bf16 g_vh[Nn * Dd], g_vl[Nn * Dd];
__device__ bf16 g_atth[Nn * Dd], g_attl[Nn * Dd];
__device__ bf16 g_t1h[Nn * DFFf], g_t1l[Nn * DFFf];
__device__ bf16 g_wqh[Ll * Dd * Dd], g_wql[Ll * Dd * Dd];
__device__ bf16 g_wkh[Ll * Dd * Dd], g_wkl[Ll * Dd * Dd];
__device__ bf16 g_wvh[Ll * Dd * Dd], g_wvl[Ll * Dd * Dd];
__device__ bf16 g_woh[Ll * Dd * Dd], g_wol[Ll * Dd * Dd];
__device__ bf16 g_w1h[Ll * Dd * DFFf], g_w1l[Ll * Dd * DFFf];
__device__ bf16 g_w2h[Ll * DFFf * Dd], g_w2l[Ll * DFFf * Dd];

// ---------------- embedding gather (+split) ----------------
__global__ void embed_kernel(const int* __restrict__ nt, const float* __restrict__ emb,
                             float* __restrict__ x, bf16* __restrict__ xh, bf16* __restrict__ xl) {
    int i = blockIdx.x;
    int d = threadIdx.x;
    float v = emb[nt[i] * Dd + d];
    x[i * Dd + d] = v;
    bf16 h = __float2bfloat16(v);
    xh[i * Dd + d] = h;
    xl[i * Dd + d] = __float2bfloat16(v - __bfloat162float(h));
}

__global__ void cvt_e8_kernel(const int* __restrict__ e, unsigned char* __restrict__ o) {
    int i = blockIdx.x * blockDim.x + threadIdx.x;
    int4 v = ((const int4*)e)[i];
    uchar4 u;
    u.x = (unsigned char)v.x; u.y = (unsigned char)v.y;
    u.z = (unsigned char)v.z; u.w = (unsigned char)v.w;
    ((uchar4*)o)[i] = u;
}

// ---------------- weight transpose + split ----------------
__device__ __forceinline__ void wsplit_body(const float* __restrict__ Wl, bf16* __restrict__ Thl,
                                            bf16* __restrict__ Tll, int Kd, int Nc) {
    __shared__ float sh[32][33], slo[32][33];
    int n0 = blockIdx.x << 5, k0 = blockIdx.y << 5;
    int tx = threadIdx.x, ty = threadIdx.y;
#pragma unroll
    for (int r = 0; r < 4; r++) {
        int kk = ty + (r << 3);
        float v = Wl[(size_t)(k0 + kk) * Nc + n0 + tx];
        float h = __bfloat162float(__float2bfloat16(v));
        sh[kk][tx] = h;
        slo[kk][tx] = v - h;
    }
    __syncthreads();
#pragma unroll
    for (int r = 0; r < 4; r++) {
        int nn = ty + (r << 3);
        Thl[(size_t)(n0 + nn) * Kd + k0 + tx] = __float2bfloat16(sh[tx][nn]);
        Tll[(size_t)(n0 + nn) * Kd + k0 + tx] = __float2bfloat16(slo[tx][nn]);
    }
}

__global__ void wsplit_kernel(const float* __restrict__ W, bf16* __restrict__ Th,
                              bf16* __restrict__ Tl, int Kd, int Nc) {
    wsplit_body(W + (size_t)blockIdx.z * Kd * Nc, Th + (size_t)blockIdx.z * Kd * Nc,
                Tl + (size_t)blockIdx.z * Kd * Nc, Kd, Nc);
}

__global__ void wsplit4_kernel(const float* __restrict__ Wq, const float* __restrict__ Wk,
                               const float* __restrict__ Wv, const float* __restrict__ Wo,
                               bf16* __restrict__ qh, bf16* __restrict__ ql,
                               bf16* __restrict__ kh, bf16* __restrict__ kl,
                               bf16* __restrict__ vh, bf16* __restrict__ vl,
                               bf16* __restrict__ oh, bf16* __restrict__ ol) {
    int l = blockIdx.z >> 2, w = blockIdx.z & 3;
    size_t off = (size_t)l * Dd * Dd;
    const float* W = (w == 0) ? Wq : (w == 1) ? Wk : (w == 2) ? Wv : Wo;
    bf16* Th = (w == 0) ? qh : (w == 1) ? kh : (w == 2) ? vh : oh;
    bf16* Tl = (w == 0) ? ql : (w == 1) ? kl : (w == 2) ? vl : ol;
    wsplit_body(W + off, Th + off, Tl + off, Dd, Dd);
}

// ---------------- split-bf16 HMMA GEMM, cp.async 2-stage pipeline (R13) ----------------
#define GEMM_SMEM 61440
template <int ACT, int OSPLIT>
__device__ __forceinline__ void hmma_gemm_body(
    const bf16* __restrict__ Ah, const bf16* __restrict__ Al,
    const bf16* __restrict__ Bh, const bf16* __restrict__ Bl,
    const float* __restrict__ bias, float* __restrict__ Cf,
    bf16* __restrict__ Ch, bf16* __restrict__ Cl,
    int Kd, int kbeg, int kslice, int Nc) {
    extern __shared__ bf16 gsm[];
    const int tid = threadIdx.x;
    const int wid = tid >> 5, lane = tid & 31;
    const int i0 = blockIdx.y << 7, j0 = blockIdx.x << 6;
    const int mw = (wid & 3) << 5;
    const int nw = (wid >> 2) << 5;

    float acc[2][4][4];
#pragma unroll
    for (int a = 0; a < 2; a++)
#pragma unroll
        for (int b = 0; b < 4; b++)
#pragma unroll
            for (int cc = 0; cc < 4; cc++) acc[a][b][cc] = 0.f;

    const int a_r = lane & 15;
    const int a_k = (lane >> 4) << 3;
    const int b_n = (lane & 7) + ((lane & 16) >> 1);
    const int b_k = lane & 8;

    uint32_t uAh[2] = {smem_u32(gsm), smem_u32(gsm + 5120)};
    uint32_t uAl[2] = {smem_u32(gsm + 10240), smem_u32(gsm + 15360)};
    uint32_t uBh[2] = {smem_u32(gsm + 20480), smem_u32(gsm + 23040)};
    uint32_t uBl[2] = {smem_u32(gsm + 25600), smem_u32(gsm + 28160)};

    const int r = tid >> 1, hf = (tid & 1) << 4;
    const int tb = tid & 127;
    const int rb = tb >> 1, hb = (tb & 1) << 4;
    const bf16* Bsel = (tid < 128) ? Bh : Bl;
    const uint32_t aoff = (uint32_t)((r * 40 + hf) << 1);
    const uint32_t boff = (uint32_t)((rb * 40 + hb) << 1);

    {
        const bf16* pAh = Ah + (size_t)(i0 + r) * Kd + kbeg + hf;
        const bf16* pAl = Al + (size_t)(i0 + r) * Kd + kbeg + hf;
        cpa16(uAh[0] + aoff, pAh);
        cpa16(uAh[0] + aoff + 16, pAh + 8);
        cpa16(uAl[0] + aoff, pAl);
        cpa16(uAl[0] + aoff + 16, pAl + 8);
        const bf16* pB = Bsel + (size_t)(j0 + rb) * Kd + kbeg + hb;
        uint32_t ub = (tid < 128) ? uBh[0] : uBl[0];
        cpa16(ub + boff, pB);
        cpa16(ub + boff + 16, pB + 8);
    }
    CP_COMMIT();

    const int nch = kslice >> 5;
    for (int c = 0; c < nch; c++) {
        const int buf = c & 1;
        CP_WAIT(0);
        __syncthreads();

        if (c + 1 < nch) {
            int kt = kbeg + ((c + 1) << 5);
            int nb = buf ^ 1;
            const bf16* pAh = Ah + (size_t)(i0 + r) * Kd + kt + hf;
            const bf16* pAl = Al + (size_t)(i0 + r) * Kd + kt + hf;
            cpa16(uAh[nb] + aoff, pAh);
            cpa16(uAh[nb] + aoff + 16, pAh + 8);
            cpa16(uAl[nb] + aoff, pAl);
            cpa16(uAl[nb] + aoff + 16, pAl + 8);
            const bf16* pB = Bsel + (size_t)(j0 + rb) * Kd + kt + hb;
            uint32_t ub = (tid < 128) ? uBh[nb] : uBl[nb];
            cpa16(ub + boff, pB);
            cpa16(ub + boff + 16, pB + 8);
        }
        CP_COMMIT();

#pragma unroll
        for (int ks = 0; ks < 2; ks++) {
            const int kk = ks << 4;
            uint32_t ah[2][4], al[2][4], bhf[2][4], blf[2][4];
#pragma unroll
            for (int mf = 0; mf < 2; mf++) {
                uint32_t off = (uint32_t)(((mw + (mf << 4) + a_r) * 40 + kk + a_k) << 1);
                ldsm4(ah[mf][0], ah[mf][1], ah[mf][2], ah[mf][3], uAh[buf] + off);
                ldsm4(al[mf][0], al[mf][1], al[mf][2], al[mf][3], uAl[buf] + off);
            }
#pragma unroll
            for (int g = 0; g < 2; g++) {
                uint32_t off = (uint32_t)(((nw + (g << 4) + b_n) * 40 + kk + b_k) << 1);
                ldsm4(bhf[g][0], bhf[g][1], bhf[g][2], bhf[g][3], uBh[buf] + off);
                ldsm4(blf[g][0], blf[g][1], blf[g][2], blf[g][3], uBl[buf] + off);
            }
#pragma unroll
            for (int mf = 0; mf < 2; mf++)
#pragma unroll
                for (int nf = 0; nf < 4; nf++) {
                    const uint32_t* ph = &bhf[nf >> 1][(nf & 1) << 1];
                    const uint32_t* pl = &blf[nf >> 1][(nf & 1) << 1];
                    mma_bf16(acc[mf][nf], ah[mf], ph);
                    mma_bf16(acc[mf][nf], ah[mf], pl);
                    mma_bf16(acc[mf][nf], al[mf], ph);
                }
        }
    }

    const int lr = lane >> 2, lc = (lane & 3) << 1;
#pragma unroll
    for (int mf = 0; mf < 2; mf++)
#pragma unroll
        for (int rp = 0; rp < 2; rp++) {
            int row = i0 + mw + (mf << 4) + lr + (rp << 3);
#pragma unroll
            for (int nf = 0; nf < 4; nf++) {
                float v0 = acc[mf][nf][(rp << 1) + 0];
                float v1 = acc[mf][nf][(rp << 1) + 1];
                int col = j0 + nw + (nf << 3) + lc;
                if (OSPLIT == 0) {
                    if (bias) {
                        v0 += bias[col];
                        v1 += bias[col + 1];
                    }
                    *(float2*)&Cf[(size_t)row * Nc + col] = make_float2(v0, v1);
                } else {
                    if (OSPLIT == 1) {
                        v0 += bias[col];
                        v1 += bias[col + 1];
                        if (ACT == 1) {
                            v0 = 0.5f * v0 * (1.0f + erff(v0 * 0.70710678118654752f));
                            v1 = 0.5f * v1 * (1.0f + erff(v1 * 0.70710678118654752f));
                        }
                    }
                    bf16 h0 = __float2bfloat16(v0), h1 = __float2bfloat16(v1);
                    Ch[(size_t)row * Nc + col] = h0;
                    Ch[(size_t)row * Nc + col + 1] = h1;
                    Cl[(size_t)row * Nc + col] = __float2bfloat16(v0 - __bfloat162float(h0));
                    Cl[(size_t)row * Nc + col + 1] = __float2bfloat16(v1 - __bfloat162float(h1));
                }
            }
        }
}

template <int ACT, int SPLIT, int OSPLIT>
__global__ void __launch_bounds__(256) hmma_gemm_kernel(
    const bf16* __restrict__ Ah, const bf16* __restrict__ Al,
    const bf16* __restrict__ Bh, const bf16* __restrict__ Bl,
    const float* __restrict__ bias, float* __restrict__ Cf,
    bf16* __restrict__ Ch, bf16* __restrict__ Cl, int Kd, int Nc) {
    int kslice = Kd / SPLIT;
    int kbeg = blockIdx.z * kslice;
    float* Cz = (SPLIT > 1) ? Cf + (size_t)blockIdx.z * Nn * Nc : Cf;
    hmma_gemm_body<ACT, OSPLIT>(Ah, Al, Bh, Bl, SPLIT > 1 ? nullptr : bias, Cz, Ch, Cl,
                                Kd, kbeg, kslice, Nc);
}

__global__ void __launch_bounds__(256) hmma_qkv_kernel(
    const bf16* __restrict__ Ah, const bf16* __restrict__ Al,
    const bf16* __restrict__ Bh0, const bf16* __restrict__ Bl0,
    const bf16* __restrict__ Bh1, const bf16* __restrict__ Bl1,
    const bf16* __restrict__ Bh2, const bf16* __restrict__ Bl2,
    bf16* __restrict__ qh, bf16* __restrict__ ql, bf16* __restrict__ kh,
    bf16* __restrict__ kl, bf16* __restrict__ vh, bf16* __restrict__ vl) {
    int z = blockIdx.z;
    const bf16* Bh = (z == 0) ? Bh0 : (z == 1) ? Bh1 : Bh2;
    const bf16* Bl = (z == 0) ? Bl0 : (z == 1) ? Bl1 : Bl2;
    bf16* Ch = (z == 0) ? qh : (z == 1) ? kh : vh;
    bf16* Cl = (z == 0) ? ql : (z == 1) ? kl : vl;
    hmma_gemm_body<0, 2>(Ah, Al, Bh, Bl, nullptr, nullptr, Ch, Cl, Dd, 0, Dd, Dd);
}

// ---------------- HMMA flash attention v5 ----------------
// 2-term S; K AND V double-buffered; ONE cp.async group + ONE wait + ONE bar per tile.
// Dynamic smem layout (bf16 el): Qh @0 (2560), Kh @2560 (4x2560), Kl @12800 (4x2560),
// Vh @23040 (4x2560), Vl @33280 (4x2560). Total 43520 el = 87040 B.
#define ATTN_SMEM 87040
__global__ void __launch_bounds__(256) attn_hmma_kernel(
    const bf16* __restrict__ Qh, const bf16* __restrict__ Ql,
    const bf16* __restrict__ Kh, const bf16* __restrict__ Kl,
    const bf16* __restrict__ Vh, const bf16* __restrict__ Vl,
    const unsigned char* __restrict__ E8, const float* __restrict__ ebl,
    bf16* __restrict__ Oh, bf16* __restrict__ Ol) {
    extern __shared__ bf16 dsm[];
    __shared__ float s_eb[8];

    const int h = blockIdx.y;
    const int i0 = blockIdx.x << 6;
    const int tid = threadIdx.x;
    const int wid = tid >> 5, lane = tid & 31;
    const int gid = wid >> 2;
    const int mw = (wid & 3) << 4;
    const int gt = tid & 127;

    if (tid < NEDGEe) s_eb[tid] = ebl[tid * Hh + h] * 1.4426950408889634f;

    const int a_r = lane & 15, a_k = (lane >> 4) << 3;
    const int b_n = (lane & 7) + ((lane & 16) >> 1), b_k = lane & 8;
    const int lr = lane >> 2, lc = (lane & 3) << 1;

    const uint32_t uQh = smem_u32(dsm);
    uint32_t uKh[2], uKl[2], uVh[2], uVl[2];
    uKh[0] = smem_u32(dsm + 2560 + (gid * 2) * 2560);
    uKh[1] = smem_u32(dsm + 2560 + (gid * 2 + 1) * 2560);
    uKl[0] = smem_u32(dsm + 12800 + (gid * 2) * 2560);
    uKl[1] = smem_u32(dsm + 12800 + (gid * 2 + 1) * 2560);
    uVh[0] = smem_u32(dsm + 23040 + (gid * 2) * 2560);
    uVh[1] = smem_u32(dsm + 23040 + (gid * 2 + 1) * 2560);
    uVl[0] = smem_u32(dsm + 33280 + (gid * 2) * 2560);
    uVl[1] = smem_u32(dsm + 33280 + (gid * 2 + 1) * 2560);

    const int qr = gt >> 1, qh4 = (gt & 1) << 4;
    const uint32_t soff0 = (uint32_t)((qr * 40 + qh4) << 1);
    const size_t ghead = (size_t)h * DKk + qh4;

    // prologue: K+V tile 0 for this group, one commit group
    {
        size_t rbase = (size_t)(gid * 64 + qr) * Dd + ghead;
        cpa16(uKh[0] + soff0, Kh + rbase);
        cpa16(uKh[0] + soff0 + 16, Kh + rbase + 8);
        cpa16(uKl[0] + soff0, Kl + rbase);
        cpa16(uKl[0] + soff0 + 16, Kl + rbase + 8);
        cpa16(uVh[0] + soff0, Vh + rbase);
        cpa16(uVh[0] + soff0 + 16, Vh + rbase + 8);
        cpa16(uVl[0] + soff0, Vl + rbase);
        cpa16(uVl[0] + soff0 + 16, Vl + rbase + 8);
    }
    CP_COMMIT();
    if (gid == 0) {
        const bf16* p = Qh + (size_t)(i0 + qr) * Dd + ghead;
        *(uint4*)(dsm + qr * 40 + qh4) = *(const uint4*)p;
        *(uint4*)(dsm + qr * 40 + qh4 + 8) = *(const uint4*)(p + 8);
    }
    __syncthreads();

    float of[4][4];
#pragma unroll
    for (int a = 0; a < 4; a++)
#pragma unroll
        for (int b = 0; b < 4; b++) of[a][b] = 0.f;
    float m0 = -1e30f, m1 = -1e30f, l0 = 0.f, l1 = 0.f;
    const float scale2 = 0.17677669529663687f * 1.4426950408889634f;
    const size_t r0e = (size_t)(i0 + mw + lr) * Nn;
    const size_t r1e = (size_t)(i0 + mw + lr + 8) * Nn;

    for (int t = 0; t < 16; t++) {
        const int jt = ((t << 1) + gid) << 6;
        const int buf = t & 1;
        CP_WAIT(0);
        GBAR(gid + 1);  // tile t data visible group-wide; prior reads of buf^1 done

        // issue K+V for tile t+1 into the other buffer (one group)
        if (t + 1 < 16) {
            size_t rbase = (size_t)(jt + 128 + qr) * Dd + ghead;
            int nb = buf ^ 1;
            cpa16(uKh[nb] + soff0, Kh + rbase);
            cpa16(uKh[nb] + soff0 + 16, Kh + rbase + 8);
            cpa16(uKl[nb] + soff0, Kl + rbase);
            cpa16(uKl[nb] + soff0 + 16, Kl + rbase + 8);
            cpa16(uVh[nb] + soff0, Vh + rbase);
            cpa16(uVh[nb] + soff0 + 16, Vh + rbase + 8);
            cpa16(uVl[nb] + soff0, Vl + rbase);
            cpa16(uVl[nb] + soff0 + 16, Vl + rbase + 8);
        }
        CP_COMMIT();

        unsigned short eu0[8], eu1[8];
#pragma unroll
        for (int nf = 0; nf < 8; nf++) {
            eu0[nf] = *(const unsigned short*)&E8[r0e + jt + (nf << 3) + lc];
            eu1[nf] = *(const unsigned short*)&E8[r1e + jt + (nf << 3) + lc];
        }

        // ---- S = Qh·(Kh+Kl) ----
        float sf[8][4];
#pragma unroll
        for (int nf = 0; nf < 8; nf++)
#pragma unroll
            for (int cc = 0; cc < 4; cc++) sf[nf][cc] = 0.f;
#pragma unroll
        for (int ks = 0; ks < 2; ks++) {
            const int kk = ks << 4;
            uint32_t aqh[4];
            uint32_t offa = (uint32_t)(((mw + a_r) * 40 + kk + a_k) << 1);
            ldsm4(aqh[0], aqh[1], aqh[2], aqh[3], uQh + offa);
#pragma unroll
            for (int g = 0; g < 4; g++) {
                uint32_t bkh[4], bkl[4];
                uint32_t offb = (uint32_t)((((g << 4) + b_n) * 40 + kk + b_k) << 1);
                ldsm4(bkh[0], bkh[1], bkh[2], bkh[3], uKh[buf] + offb);
                ldsm4(bkl[0], bkl[1], bkl[2], bkl[3], uKl[buf] + offb);
#pragma unroll
                for (int sub = 0; sub < 2; sub++) {
                    int nf = (g << 1) + sub;
                    mma_bf16(sf[nf], aqh, &bkh[sub << 1]);
                    mma_bf16(sf[nf], aqh, &bkl[sub << 1]);
                }
            }
        }

        float mx0 = -1e30f, mx1 = -1e30f;
#pragma unroll
        for (int nf = 0; nf < 8; nf++) {
            sf[nf][0] = fmaf(sf[nf][0], scale2, s_eb[eu0[nf] & 0xffu]);
            sf[nf][1] = fmaf(sf[nf][1], scale2, s_eb[eu0[nf] >> 8]);
            sf[nf][2] = fmaf(sf[nf][2], scale2, s_eb[eu1[nf] & 0xffu]);
            sf[nf][3] = fmaf(sf[nf][3], scale2, s_eb[eu1[nf] >> 8]);
            mx0 = fmaxf(mx0, fmaxf(sf[nf][0], sf[nf][1]));
            mx1 = fmaxf(mx1, fmaxf(sf[nf][2], sf[nf][3]));
        }
        mx0 = fmaxf(mx0, __shfl_xor_sync(0xffffffffu, mx0, 1));
        mx0 = fmaxf(mx0, __shfl_xor_sync(0xffffffffu, mx0, 2));
        mx1 = fmaxf(mx1, __shfl_xor_sync(0xffffffffu, mx1, 1));
        mx1 = fmaxf(mx1, __shfl_xor_sync(0xffffffffu, mx1, 2));
        float mn0 = fmaxf(m0, mx0), mn1 = fmaxf(m1, mx1);
        float al0 = ex2f(m0 - mn0), al1 = ex2f(m1 - mn1);
        m0 = mn0;
        m1 = mn1;
#pragma unroll
        for (int nf = 0; nf < 4; nf++) {
            of[nf][0] *= al0;
            of[nf][1] *= al0;
            of[nf][2] *= al1;
            of[nf][3] *= al1;
        }

        float ps0 = 0.f, ps1 = 0.f;
        uint32_t aph[4][4];
#pragma unroll
        for (int nf = 0; nf < 8; nf++) {
            float p0 = ex2f(sf[nf][0] - mn0);
            float p1 = ex2f(sf[nf][1] - mn0);
            float p2 = ex2f(sf[nf][2] - mn1);
            float p3 = ex2f(sf[nf][3] - mn1);
            ps0 += p0 + p1;
            ps1 += p2 + p3;
            int ks = nf >> 1, base = (nf & 1) << 1;
            aph[ks][base + 0] = pack2bf(p0, p1);
            aph[ks][base + 1] = pack2bf(p2, p3);
        }
        ps0 += __shfl_xor_sync(0xffffffffu, ps0, 1);
        ps0 += __shfl_xor_sync(0xffffffffu, ps0, 2);
        ps1 += __shfl_xor_sync(0xffffffffu, ps1, 1);
        ps1 += __shfl_xor_sync(0xffffffffu, ps1, 2);
        l0 = l0 * al0 + ps0;
        l1 = l1 * al1 + ps1;

        // ---- O += P·(Vh+Vl), same buffer, no extra wait ----
#pragma unroll
        for (int ks = 0; ks < 4; ks++) {
            const int kk = ks << 4;
#pragma unroll
            for (int dg = 0; dg < 2; dg++) {
                uint32_t bvh[4], bvl[4];
                uint32_t offv = (uint32_t)(((kk + a_r) * 40 + (dg << 4) + a_k) << 1);
                ldsm4t(bvh[0], bvh[1], bvh[2], bvh[3], uVh[buf] + offv);
                ldsm4t(bvl[0], bvl[1], bvl[2], bvl[3], uVl[buf] + offv);
#pragma unroll
                for (int sub = 0; sub < 2; sub++) {
                    int nf = (dg << 1) + sub;
                    mma_bf16(of[nf], aph[ks], &bvh[sub << 1]);
                    mma_bf16(of[nf], aph[ks], &bvl[sub << 1]);
                }
            }
        }
    }

    // ---- split-softmax merge ----
    CP_WAIT(0);
    __syncthreads();
    float* mg = (float*)dsm;
    float* lg = mg + 256;
    float* og = lg + 256;
    if (gid == 1) {
        mg[gt * 2] = m0;
        mg[gt * 2 + 1] = m1;
        lg[gt * 2] = l0;
        lg[gt * 2 + 1] = l1;
#pragma unroll
        for (int nf = 0; nf < 4; nf++)
#pragma unroll
            for (int c = 0; c < 4; c++) og[gt * 16 + nf * 4 + c] = of[nf][c];
    }
    __syncthreads();
    if (gid == 0) {
        float mb0 = mg[gt * 2], mb1 = mg[gt * 2 + 1];
        float lb0 = lg[gt * 2], lb1 = lg[gt * 2 + 1];
        float mn0 = fmaxf(m0, mb0), mn1 = fmaxf(m1, mb1);
        float a0 = ex2f(m0 - mn0), bb0 = ex2f(mb0 - mn0);
        float a1 = ex2f(m1 - mn1), bb1 = ex2f(mb1 - mn1);
        float inv0 = 1.0f / (l0 * a0 + lb0 * bb0);
        float inv1 = 1.0f / (l1 * a1 + lb1 * bb1);
        int row0 = i0 + mw + lr, row1 = row0 + 8;
#pragma unroll
        for (int nf = 0; nf < 4; nf++) {
            int col = h * DKk + (nf << 3) + lc;
            float v0 = (of[nf][0] * a0 + og[gt * 16 + nf * 4 + 0] * bb0) * inv0;
            float v1 = (of[nf][1] * a0 + og[gt * 16 + nf * 4 + 1] * bb0) * inv0;
            float v2 = (of[nf][2] * a1 + og[gt * 16 + nf * 4 + 2] * bb1) * inv1;
            float v3 = (of[nf][3] * a1 + og[gt * 16 + nf * 4 + 3] * bb1) * inv1;
            float h0 = __bfloat162float(__float2bfloat16(v0));
            float h1 = __bfloat162float(__float2bfloat16(v1));
            float h2 = __bfloat162float(__float2bfloat16(v2));
            float h3 = __bfloat162float(__float2bfloat16(v3));
            *(uint32_t*)&Oh[(size_t)row0 * Dd + col] = pack2bf(h0, h1);
            *(uint32_t*)&Oh[(size_t)row1 * Dd + col] = pack2bf(h2, h3);
            *(uint32_t*)&Ol[(size_t)row0 * Dd + col] = pack2bf(v0 - h0, v1 - h1);
            *(uint32_t*)&Ol[(size_t)row1 * Dd + col] = pack2bf(v2 - h2, v3 - h3);
        }
    }
}

// ---------------- reduce + bias + residual + LayerNorm (R13 1-row version) ----------------
template <int S>
__global__ void addln_red_kernel(float* __restrict__ x, const float* __restrict__ part,
                                 const float* __restrict__ bias, const float* __restrict__ g,
                                 const float* __restrict__ b, bf16* __restrict__ xh,
                                 bf16* __restrict__ xl) {
    int i = blockIdx.x, d = threadIdx.x;
    int lane = d & 31, w = d >> 5;
    __shared__ float ws[8];
    float v = x[i * Dd + d] + bias[d];
#pragma unroll
    for (int s = 0; s < S; s++) v += part[(size_t)s * Nn * Dd + (size_t)i * Dd + d];
    float t = v;
#pragma unroll
    for (int off = 16; off > 0; off >>= 1) t += __shfl_xor_sync(0xffffffffu, t, off);
    if (lane == 0) ws[w] = t;
    __syncthreads();
    float mean = (ws[0] + ws[1] + ws[2] + ws[3] + ws[4] + ws[5] + ws[6] + ws[7]) * (1.0f / Dd);
    float dv = v - mean;
    t = dv * dv;
#pragma unroll
    for (int off = 16; off > 0; off >>= 1) t += __shfl_xor_sync(0xffffffffu, t, off);
    __syncthreads();
    if (lane == 0) ws[w] = t;
    __syncthreads();
    float var = (ws[0] + ws[1] + ws[2] + ws[3] + ws[4] + ws[5] + ws[6] + ws[7]) * (1.0f / Dd);
    float outv = dv * rsqrtf(var + 1e-5f) * g[d] + b[d];
    x[i * Dd + d] = outv;
    bf16 h = __float2bfloat16(outv);
    xh[i * Dd + d] = h;
    xl[i * Dd + d] = __float2bfloat16(outv - __bfloat162float(h));
}

__global__ void pool_kernel(const float* __restrict__ x, float* __restrict__ p) {
    int j = blockIdx.x * 32 + threadIdx.x;
    int yy = threadIdx.y;
    float s = 0.f, mx = -1e30f;
    for (int i = yy; i < Nn; i += 8) {
        float v = x[(size_t)i * Dd + j];
        s += v;
        mx = fmaxf(mx, v);
    }
    __shared__ float ss[8][33], sm[8][33];
    ss[yy][threadIdx.x] = s;
    sm[yy][threadIdx.x] = mx;
    __syncthreads();
    if (yy == 0) {
        for (int k2 = 1; k2 < 8; k2++) {
            s += ss[k2][threadIdx.x];
            mx = fmaxf(mx, sm[k2][threadIdx.x]);
        }
        p[j] = s * (1.0f / Nn);
        p[Dd + j] = mx;
    }
}

__global__ void head_kernel(const float* __restrict__ pooled, const float* __restrict__ Wr,
                            const float* __restrict__ br, float* __restrict__ out) {
    __shared__ float sp[2 * Dd];
    int d = threadIdx.x;
    sp[d] = pooled[d];
    sp[d + Dd] = pooled[d + Dd];
    __syncthreads();
    float acc = br[d];
#pragma unroll 8
    for (int k2 = 0; k2 < 2 * Dd; k2++) acc = fmaf(sp[k2], Wr[(size_t)k2 * Dd + d], acc);
    out[d] = acc;
}

// ---------------- host launcher ----------------
extern "C" void kernel_launch(void* const* d_in, const int* in_sizes, int n_in,
                              void* d_out, int out_size) {
    const int* node_types = (const int*)d_in[0];
    const int* edge_idx = (const int*)d_in[1];
    const float* node_emb = (const float*)d_in[2];
    const float* Wq = (const float*)d_in[3];
    const float* Wk = (const float*)d_in[4];
    const float* Wv = (const float*)d_in[5];
    const float* Wo = (const float*)d_in[6];
    const float* bo = (const float*)d_in[7];
    const float* eb = (const float*)d_in[8];
    const float* W1 = (const float*)d_in[9];
    const float* b1 = (const float*)d_in[10];
    const float* W2 = (const float*)d_in[11];
    const float* b2 = (const float*)d_in[12];
    const float* ln1g = (const float*)d_in[13];
    const float* ln1b = (const float*)d_in[14];
    const float* ln2g = (const float*)d_in[15];
    const float* ln2b = (const float*)d_in[16];
    const float* Wr = (const float*)d_in[17];
    const float* brr = (const float*)d_in[18];
    float* out = (float*)d_out;

    float *x, *part, *pool;
    unsigned char* e8;
    bf16 *xh, *xl, *qh, *ql, *kh, *kl, *vh, *vl, *atth, *attl, *t1h, *t1l;
    bf16 *wqh, *wql, *wkh, *wkl, *wvh, *wvl, *woh, *wol, *w1h, *w1l, *w2h, *w2l;
    cudaGetSymbolAddress((void**)&x, g_x);
    cudaGetSymbolAddress((void**)&part, g_part);
    cudaGetSymbolAddress((void**)&pool, g_pool);
    cudaGetSymbolAddress((void**)&e8, g_e8);
    cudaGetSymbolAddress((void**)&xh, g_xh);
    cudaGetSymbolAddress((void**)&xl, g_xl);
    cudaGetSymbolAddress((void**)&qh, g_qh);
    cudaGetSymbolAddress((void**)&ql, g_ql);
    cudaGetSymbolAddress((void**)&kh, g_kh);
    cudaGetSymbolAddress((void**)&kl, g_kl);
    cudaGetSymbolAddress((void**)&vh, g_vh);
    cudaGetSymbolAddress((void**)&vl, g_vl);
    cudaGetSymbolAddress((void**)&atth, g_atth);
    cudaGetSymbolAddress((void**)&attl, g_attl);
    cudaGetSymbolAddress((void**)&t1h, g_t1h);
    cudaGetSymbolAddress((void**)&t1l, g_t1l);
    cudaGetSymbolAddress((void**)&wqh, g_wqh);
    cudaGetSymbolAddress((void**)&wql, g_wql);
    cudaGetSymbolAddress((void**)&wkh, g_wkh);
    cudaGetSymbolAddress((void**)&wkl, g_wkl);
    cudaGetSymbolAddress((void**)&wvh, g_wvh);
    cudaGetSymbolAddress((void**)&wvl, g_wvl);
    cudaGetSymbolAddress((void**)&woh, g_woh);
    cudaGetSymbolAddress((void**)&wol, g_wol);
    cudaGetSymbolAddress((void**)&w1h, g_w1h);
    cudaGetSymbolAddress((void**)&w1l, g_w1l);
    cudaGetSymbolAddress((void**)&w2h, g_w2h);
    cudaGetSymbolAddress((void**)&w2l, g_w2l);

    cudaFuncSetAttribute(attn_hmma_kernel, cudaFuncAttributeMaxDynamicSharedMemorySize,
                         ATTN_SMEM);
    cudaFuncSetAttribute(hmma_qkv_kernel, cudaFuncAttributeMaxDynamicSharedMemorySize,
                         GEMM_SMEM);
    cudaFuncSetAttribute(hmma_gemm_kernel<0, 2, 0>, cudaFuncAttributeMaxDynamicSharedMemorySize,
                         GEMM_SMEM);
    cudaFuncSetAttribute(hmma_gemm_kernel<1, 1, 1>, cudaFuncAttributeMaxDynamicSharedMemorySize,
                         GEMM_SMEM);

    embed_kernel<<<Nn, Dd>>>(node_types, node_emb, x, xh, xl);
    cvt_e8_kernel<<<(Nn * Nn / 4) / 256, 256>>>(edge_idx, e8);

    wsplit4_kernel<<<dim3(8, 8, 4 * Ll), dim3(32, 8)>>>(Wq, Wk, Wv, Wo, wqh, wql, wkh, wkl,
                                                        wvh, wvl, woh, wol);
    wsplit_kernel<<<dim3(32, 8, Ll), dim3(32, 8)>>>(W1, w1h, w1l, Dd, DFFf);
    wsplit_kernel<<<dim3(8, 32, Ll), dim3(32, 8)>>>(W2, w2h, w2l, DFFf, Dd);

    for (int l = 0; l < Ll; l++) {
        size_t wo256 = (size_t)l * Dd * Dd;
        size_t woff1 = (size_t)l * Dd * DFFf;
        hmma_qkv_kernel<<<dim3(4, 16, 3), 256, GEMM_SMEM>>>(
            xh, xl, wqh + wo256, wql + wo256, wkh + wo256, wkl + wo256, wvh + wo256,
            wvl + wo256, qh, ql, kh, kl, vh, vl);

        attn_hmma_kernel<<<dim3(Nn / 64, Hh), 256, ATTN_SMEM>>>(
            qh, ql, kh, kl, vh, vl, e8, eb + l * NEDGEe * Hh, atth, attl);

        hmma_gemm_kernel<0, 2, 0><<<dim3(4, 16, 2), 256, GEMM_SMEM>>>(
            atth, attl, woh + wo256, wol + wo256, nullptr, part, nullptr, nullptr, Dd, Dd);
        addln_red_kernel<2><<<Nn, Dd>>>(x, part, bo + l * Dd, ln1g + l * Dd, ln1b + l * Dd, xh,
                                        xl);

        hmma_gemm_kernel<1, 1, 1><<<dim3(16, 16, 1), 256, GEMM_SMEM>>>(
            xh, xl, w1h + woff1, w1l + woff1, b1 + l * DFFf, nullptr, t1h, t1l, Dd, DFFf);

        hmma_gemm_kernel<0, 2, 0><<<dim3(4, 16, 2), 256, GEMM_SMEM>>>(
            t1h, t1l, w2h + woff1, w2l + woff1, nullptr, part, nullptr, nullptr, DFFf, Dd);
        addln_red_kernel<2><<<Nn, Dd>>>(x, part, b2 + l * Dd, ln2g + l * Dd, ln2b + l * Dd, xh,
                                        xl);
    }

    pool_kernel<<<Dd / 32, dim3(32, 8)>>>(x, pool);
    head_kernel<<<1, Dd>>>(pool, Wr, brr, out);
}

// round 16
// speedup vs baseline: 1.0240x; 1.0240x over previous
#include <cuda_runtime.h>
#include <cuda_bf16.h>
#include <stdint.h>
#include <math.h>

#define Nn 2048
#define Dd 256
#define Hh 8
#define DKk 32
#define Ll 4
#define DFFf 1024
#define NEDGEe 5

typedef __nv_bfloat16 bf16;

// ---------------- portable MMA helpers (validated R8-R14) ----------------
__device__ __forceinline__ uint32_t smem_u32(const void* p) {
    uint32_t a;
    asm("{ .reg .u64 t; cvta.to.shared.u64 t, %1; cvt.u32.u64 %0, t; }" : "=r"(a) : "l"(p));
    return a;
}
__device__ __forceinline__ void ldsm4(uint32_t& r0, uint32_t& r1, uint32_t& r2, uint32_t& r3,
                                      uint32_t addr) {
    asm volatile("ldmatrix.sync.aligned.m8n8.x4.shared.b16 {%0,%1,%2,%3}, [%4];"
                 : "=r"(r0), "=r"(r1), "=r"(r2), "=r"(r3)
                 : "r"(addr));
}
__device__ __forceinline__ void ldsm4t(uint32_t& r0, uint32_t& r1, uint32_t& r2, uint32_t& r3,
                                       uint32_t addr) {
    asm volatile("ldmatrix.sync.aligned.m8n8.x4.trans.shared.b16 {%0,%1,%2,%3}, [%4];"
                 : "=r"(r0), "=r"(r1), "=r"(r2), "=r"(r3)
                 : "r"(addr));
}
__device__ __forceinline__ void mma_bf16(float* d, const uint32_t* a, const uint32_t* b) {
    asm volatile(
        "mma.sync.aligned.m16n8k16.row.col.f32.bf16.bf16.f32 "
        "{%0,%1,%2,%3}, {%4,%5,%6,%7}, {%8,%9}, {%0,%1,%2,%3};"
        : "+f"(d[0]), "+f"(d[1]), "+f"(d[2]), "+f"(d[3])
        : "r"(a[0]), "r"(a[1]), "r"(a[2]), "r"(a[3]), "r"(b[0]), "r"(b[1]));
}
__device__ __forceinline__ uint32_t pack2bf(float a, float b) {
    uint32_t r;
    asm("cvt.rn.bf16x2.f32 %0, %1, %2;" : "=r"(r) : "f"(b), "f"(a));
    return r;
}
__device__ __forceinline__ float ex2f(float x) {
    float y;
    asm("ex2.approx.f32 %0, %1;" : "=f"(y) : "f"(x));
    return y;
}
__device__ __forceinline__ void cpa16(uint32_t dst, const void* src) {
    asm volatile("cp.async.cg.shared.global [%0], [%1], 16;" :: "r"(dst), "l"(src));
}
#define CP_COMMIT() asm volatile("cp.async.commit_group;" ::: "memory")
#define CP_WAIT(n) asm volatile("cp.async.wait_group %0;" :: "n"(n) : "memory")
#define GBAR(id) asm volatile("bar.sync %0, %1;" :: "r"(id), "r"(128) : "memory")

// ---------------- scratch ----------------
__device__ float g_x[Nn * Dd];
__device__ float g_part[2 * Nn * Dd];
__device__ unsigned char g_e8[Nn * Nn];
__device__ float g_pool[2 * Dd];
__device__ bf16 g_xh[Nn * Dd], g_xl[Nn * Dd];
__device__ bf16 g_qh[Nn * Dd], g_ql[Nn * Dd];
__device__ bf16 g_kh[Nn * Dd], g_kl[Nn * Dd];
__device__ bf16 g_vh[Nn * Dd], g_vl[Nn * Dd];
__device__ bf16 g_atth[Nn * Dd], g_attl[Nn * Dd];
__device__ bf16 g_t1h[Nn * DFFf], g_t1l[Nn * DFFf];
__device__ bf16 g_wqh[Ll * Dd * Dd], g_wql[Ll * Dd * Dd];
__device__ bf16 g_wkh[Ll * Dd * Dd], g_wkl[Ll * Dd * Dd];
__device__ bf16 g_wvh[Ll * Dd * Dd], g_wvl[Ll * Dd * Dd];
__device__ bf16 g_woh[Ll * Dd * Dd], g_wol[Ll * Dd * Dd];
__device__ bf16 g_w1h[Ll * Dd * DFFf], g_w1l[Ll * Dd * DFFf];
__device__ bf16 g_w2h[Ll * DFFf * Dd], g_w2l[Ll * DFFf * Dd];

// ---------------- embedding gather (+split) ----------------
__global__ void embed_kernel(const int* __restrict__ nt, const float* __restrict__ emb,
                             float* __restrict__ x, bf16* __restrict__ xh, bf16* __restrict__ xl) {
    int i = blockIdx.x;
    int d = threadIdx.x;
    float v = emb[nt[i] * Dd + d];
    x[i * Dd + d] = v;
    bf16 h = __float2bfloat16(v);
    xh[i * Dd + d] = h;
    xl[i * Dd + d] = __float2bfloat16(v - __bfloat162float(h));
}

__global__ void cvt_e8_kernel(const int* __restrict__ e, unsigned char* __restrict__ o) {
    int i = blockIdx.x * blockDim.x + threadIdx.x;
    int4 v = ((const int4*)e)[i];
    uchar4 u;
    u.x = (unsigned char)v.x; u.y = (unsigned char)v.y;
    u.z = (unsigned char)v.z; u.w = (unsigned char)v.w;
    ((uchar4*)o)[i] = u;
}

// ---------------- weight transpose + split ----------------
__device__ __forceinline__ void wsplit_body(const float* __restrict__ Wl, bf16* __restrict__ Thl,
                                            bf16* __restrict__ Tll, int Kd, int Nc) {
    __shared__ float sh[32][33], slo[32][33];
    int n0 = blockIdx.x << 5, k0 = blockIdx.y << 5;
    int tx = threadIdx.x, ty = threadIdx.y;
#pragma unroll
    for (int r = 0; r < 4; r++) {
        int kk = ty + (r << 3);
        float v = Wl[(size_t)(k0 + kk) * Nc + n0 + tx];
        float h = __bfloat162float(__float2bfloat16(v));
        sh[kk][tx] = h;
        slo[kk][tx] = v - h;
    }
    __syncthreads();
#pragma unroll
    for (int r = 0; r < 4; r++) {
        int nn = ty + (r << 3);
        Thl[(size_t)(n0 + nn) * Kd + k0 + tx] = __float2bfloat16(sh[tx][nn]);
        Tll[(size_t)(n0 + nn) * Kd + k0 + tx] = __float2bfloat16(slo[tx][nn]);
    }
}

__global__ void wsplit_kernel(const float* __restrict__ W, bf16* __restrict__ Th,
                              bf16* __restrict__ Tl, int Kd, int Nc) {
    wsplit_body(W + (size_t)blockIdx.z * Kd * Nc, Th + (size_t)blockIdx.z * Kd * Nc,
                Tl + (size_t)blockIdx.z * Kd * Nc, Kd, Nc);
}

__global__ void wsplit4_kernel(const float* __restrict__ Wq, const float* __restrict__ Wk,
                               const float* __restrict__ Wv, const float* __restrict__ Wo,
                               bf16* __restrict__ qh, bf16* __restrict__ ql,
                               bf16* __restrict__ kh, bf16* __restrict__ kl,
                               bf16* __restrict__ vh, bf16* __restrict__ vl,
                               bf16* __restrict__ oh, bf16* __restrict__ ol) {
    int l = blockIdx.z >> 2, w = blockIdx.z & 3;
    size_t off = (size_t)l * Dd * Dd;
    const float* W = (w == 0) ? Wq : (w == 1) ? Wk : (w == 2) ? Wv : Wo;
    bf16* Th = (w == 0) ? qh : (w == 1) ? kh : (w == 2) ? vh : oh;
    bf16* Tl = (w == 0) ? ql : (w == 1) ? kl : (w == 2) ? vl : ol;
    wsplit_body(W + off, Th + off, Tl + off, Dd, Dd);
}

// ---------------- split-bf16 HMMA GEMM, cp.async 2-stage pipeline (R13) ----------------
#define GEMM_SMEM 61440
template <int ACT, int OSPLIT>
__device__ __forceinline__ void hmma_gemm_body(
    const bf16* __restrict__ Ah, const bf16* __restrict__ Al,
    const bf16* __restrict__ Bh, const bf16* __restrict__ Bl,
    const float* __restrict__ bias, float* __restrict__ Cf,
    bf16* __restrict__ Ch, bf16* __restrict__ Cl,
    int Kd, int kbeg, int kslice, int Nc) {
    extern __shared__ bf16 gsm[];
    const int tid = threadIdx.x;
    const int wid = tid >> 5, lane = tid & 31;
    const int i0 = blockIdx.y << 7, j0 = blockIdx.x << 6;
    const int mw = (wid & 3) << 5;
    const int nw = (wid >> 2) << 5;

    float acc[2][4][4];
#pragma unroll
    for (int a = 0; a < 2; a++)
#pragma unroll
        for (int b = 0; b < 4; b++)
#pragma unroll
            for (int cc = 0; cc < 4; cc++) acc[a][b][cc] = 0.f;

    const int a_r = lane & 15;
    const int a_k = (lane >> 4) << 3;
    const int b_n = (lane & 7) + ((lane & 16) >> 1);
    const int b_k = lane & 8;

    uint32_t uAh[2] = {smem_u32(gsm), smem_u32(gsm + 5120)};
    uint32_t uAl[2] = {smem_u32(gsm + 10240), smem_u32(gsm + 15360)};
    uint32_t uBh[2] = {smem_u32(gsm + 20480), smem_u32(gsm + 23040)};
    uint32_t uBl[2] = {smem_u32(gsm + 25600), smem_u32(gsm + 28160)};

    const int r = tid >> 1, hf = (tid & 1) << 4;
    const int tb = tid & 127;
    const int rb = tb >> 1, hb = (tb & 1) << 4;
    const bf16* Bsel = (tid < 128) ? Bh : Bl;
    const uint32_t aoff = (uint32_t)((r * 40 + hf) << 1);
    const uint32_t boff = (uint32_t)((rb * 40 + hb) << 1);

    {
        const bf16* pAh = Ah + (size_t)(i0 + r) * Kd + kbeg + hf;
        const bf16* pAl = Al + (size_t)(i0 + r) * Kd + kbeg + hf;
        cpa16(uAh[0] + aoff, pAh);
        cpa16(uAh[0] + aoff + 16, pAh + 8);
        cpa16(uAl[0] + aoff, pAl);
        cpa16(uAl[0] + aoff + 16, pAl + 8);
        const bf16* pB = Bsel + (size_t)(j0 + rb) * Kd + kbeg + hb;
        uint32_t ub = (tid < 128) ? uBh[0] : uBl[0];
        cpa16(ub + boff, pB);
        cpa16(ub + boff + 16, pB + 8);
    }
    CP_COMMIT();

    const int nch = kslice >> 5;
    for (int c = 0; c < nch; c++) {
        const int buf = c & 1;
        CP_WAIT(0);
        __syncthreads();

        if (c + 1 < nch) {
            int kt = kbeg + ((c + 1) << 5);
            int nb = buf ^ 1;
            const bf16* pAh = Ah + (size_t)(i0 + r) * Kd + kt + hf;
            const bf16* pAl = Al + (size_t)(i0 + r) * Kd + kt + hf;
            cpa16(uAh[nb] + aoff, pAh);
            cpa16(uAh[nb] + aoff + 16, pAh + 8);
            cpa16(uAl[nb] + aoff, pAl);
            cpa16(uAl[nb] + aoff + 16, pAl + 8);
            const bf16* pB = Bsel + (size_t)(j0 + rb) * Kd + kt + hb;
            uint32_t ub = (tid < 128) ? uBh[nb] : uBl[nb];
            cpa16(ub + boff, pB);
            cpa16(ub + boff + 16, pB + 8);
        }
        CP_COMMIT();

#pragma unroll
        for (int ks = 0; ks < 2; ks++) {
            const int kk = ks << 4;
            uint32_t ah[2][4], al[2][4], bhf[2][4], blf[2][4];
#pragma unroll
            for (int mf = 0; mf < 2; mf++) {
                uint32_t off = (uint32_t)(((mw + (mf << 4) + a_r) * 40 + kk + a_k) << 1);
                ldsm4(ah[mf][0], ah[mf][1], ah[mf][2], ah[mf][3], uAh[buf] + off);
                ldsm4(al[mf][0], al[mf][1], al[mf][2], al[mf][3], uAl[buf] + off);
            }
#pragma unroll
            for (int g = 0; g < 2; g++) {
                uint32_t off = (uint32_t)(((nw + (g << 4) + b_n) * 40 + kk + b_k) << 1);
                ldsm4(bhf[g][0], bhf[g][1], bhf[g][2], bhf[g][3], uBh[buf] + off);
                ldsm4(blf[g][0], blf[g][1], blf[g][2], blf[g][3], uBl[buf] + off);
            }
#pragma unroll
            for (int mf = 0; mf < 2; mf++)
#pragma unroll
                for (int nf = 0; nf < 4; nf++) {
                    const uint32_t* ph = &bhf[nf >> 1][(nf & 1) << 1];
                    const uint32_t* pl = &blf[nf >> 1][(nf & 1) << 1];
                    mma_bf16(acc[mf][nf], ah[mf], ph);
                    mma_bf16(acc[mf][nf], ah[mf], pl);
                    mma_bf16(acc[mf][nf], al[mf], ph);
                }
        }
    }

    const int lr = lane >> 2, lc = (lane & 3) << 1;
#pragma unroll
    for (int mf = 0; mf < 2; mf++)
#pragma unroll
        for (int rp = 0; rp < 2; rp++) {
            int row = i0 + mw + (mf << 4) + lr + (rp << 3);
#pragma unroll
            for (int nf = 0; nf < 4; nf++) {
                float v0 = acc[mf][nf][(rp << 1) + 0];
                float v1 = acc[mf][nf][(rp << 1) + 1];
                int col = j0 + nw + (nf << 3) + lc;
                if (OSPLIT == 0) {
                    if (bias) {
                        v0 += bias[col];
                        v1 += bias[col + 1];
                    }
                    *(float2*)&Cf[(size_t)row * Nc + col] = make_float2(v0, v1);
                } else {
                    if (OSPLIT == 1) {
                        v0 += bias[col];
                        v1 += bias[col + 1];
                        if (ACT == 1) {
                            v0 = 0.5f * v0 * (1.0f + erff(v0 * 0.70710678118654752f));
                            v1 = 0.5f * v1 * (1.0f + erff(v1 * 0.70710678118654752f));
                        }
                    }
                    bf16 h0 = __float2bfloat16(v0), h1 = __float2bfloat16(v1);
                    Ch[(size_t)row * Nc + col] = h0;
                    Ch[(size_t)row * Nc + col + 1] = h1;
                    Cl[(size_t)row * Nc + col] = __float2bfloat16(v0 - __bfloat162float(h0));
                    Cl[(size_t)row * Nc + col + 1] = __float2bfloat16(v1 - __bfloat162float(h1));
                }
            }
        }
}

template <int ACT, int SPLIT, int OSPLIT>
__global__ void __launch_bounds__(256) hmma_gemm_kernel(
    const bf16* __restrict__ Ah, const bf16* __restrict__ Al,
    const bf16* __restrict__ Bh, const bf16* __restrict__ Bl,
    const float* __restrict__ bias, float* __restrict__ Cf,
    bf16* __restrict__ Ch, bf16* __restrict__ Cl, int Kd, int Nc) {
    int kslice = Kd / SPLIT;
    int kbeg = blockIdx.z * kslice;
    float* Cz = (SPLIT > 1) ? Cf + (size_t)blockIdx.z * Nn * Nc : Cf;
    hmma_gemm_body<ACT, OSPLIT>(Ah, Al, Bh, Bl, SPLIT > 1 ? nullptr : bias, Cz, Ch, Cl,
                                Kd, kbeg, kslice, Nc);
}

__global__ void __launch_bounds__(256) hmma_qkv_kernel(
    const bf16* __restrict__ Ah, const bf16* __restrict__ Al,
    const bf16* __restrict__ Bh0, const bf16* __restrict__ Bl0,
    const bf16* __restrict__ Bh1, const bf16* __restrict__ Bl1,
    const bf16* __restrict__ Bh2, const bf16* __restrict__ Bl2,
    bf16* __restrict__ qh, bf16* __restrict__ ql, bf16* __restrict__ kh,
    bf16* __restrict__ kl, bf16* __restrict__ vh, bf16* __restrict__ vl) {
    int z = blockIdx.z;
    const bf16* Bh = (z == 0) ? Bh0 : (z == 1) ? Bh1 : Bh2;
    const bf16* Bl = (z == 0) ? Bl0 : (z == 1) ? Bl1 : Bl2;
    bf16* Ch = (z == 0) ? qh : (z == 1) ? kh : vh;
    bf16* Cl = (z == 0) ? ql : (z == 1) ? kl : vl;
    hmma_gemm_body<0, 2>(Ah, Al, Bh, Bl, nullptr, nullptr, Ch, Cl, Dd, 0, Dd, Dd);
}

// ---------------- HMMA flash attention: v3 sync structure + 2-term S ----------------
#define ATTN_SMEM 71680
__global__ void __launch_bounds__(256) attn_hmma_kernel(
    const bf16* __restrict__ Qh, const bf16* __restrict__ Ql,
    const bf16* __restrict__ Kh, const bf16* __restrict__ Kl,
    const bf16* __restrict__ Vh, const bf16* __restrict__ Vl,
    const unsigned char* __restrict__ E8, const float* __restrict__ ebl,
    bf16* __restrict__ Oh, bf16* __restrict__ Ol) {
    extern __shared__ bf16 dsm[];
    __shared__ float s_eb[8];

    const int h = blockIdx.y;
    const int i0 = blockIdx.x << 6;
    const int tid = threadIdx.x;
    const int wid = tid >> 5, lane = tid & 31;
    const int gid = wid >> 2;
    const int mw = (wid & 3) << 4;
    const int gt = tid & 127;

    if (tid < NEDGEe) s_eb[tid] = ebl[tid * Hh + h] * 1.4426950408889634f;

    const int a_r = lane & 15, a_k = (lane >> 4) << 3;
    const int b_n = (lane & 7) + ((lane & 16) >> 1), b_k = lane & 8;
    const int lr = lane >> 2, lc = (lane & 3) << 1;

    const uint32_t uQh = smem_u32(dsm);
    uint32_t uKh[2], uKl[2];
    uKh[0] = smem_u32(dsm + 5120 + (gid * 2) * 2560);
    uKh[1] = smem_u32(dsm + 5120 + (gid * 2 + 1) * 2560);
    uKl[0] = smem_u32(dsm + 15360 + (gid * 2) * 2560);
    uKl[1] = smem_u32(dsm + 15360 + (gid * 2 + 1) * 2560);
    const uint32_t uVh = smem_u32(dsm + 25600 + gid * 2560);
    const uint32_t uVl = smem_u32(dsm + 30720 + gid * 2560);

    const int qr = gt >> 1, qh4 = (gt & 1) << 4;
    const uint32_t soff0 = (uint32_t)((qr * 40 + qh4) << 1);
    const size_t ghead = (size_t)h * DKk + qh4;

    {
        const bf16* pk = Kh + (size_t)(gid * 64 + qr) * Dd + ghead;
        cpa16(uKh[0] + soff0, pk);
        cpa16(uKh[0] + soff0 + 16, pk + 8);
        const bf16* pk2 = Kl + (size_t)(gid * 64 + qr) * Dd + ghead;
        cpa16(uKl[0] + soff0, pk2);
        cpa16(uKl[0] + soff0 + 16, pk2 + 8);
    }
    CP_COMMIT();
    if (gid == 0) {
        const bf16* p = Qh + (size_t)(i0 + qr) * Dd + ghead;
        *(uint4*)(dsm + qr * 40 + qh4) = *(const uint4*)p;
        *(uint4*)(dsm + qr * 40 + qh4 + 8) = *(const uint4*)(p + 8);
    }
    __syncthreads();

    float of[4][4];
#pragma unroll
    for (int a = 0; a < 4; a++)
#pragma unroll
        for (int b = 0; b < 4; b++) of[a][b] = 0.f;
    float m0 = -1e30f, m1 = -1e30f, l0 = 0.f, l1 = 0.f;
    const float scale2 = 0.17677669529663687f * 1.4426950408889634f;
    const size_t r0e = (size_t)(i0 + mw + lr) * Nn;
    const size_t r1e = (size_t)(i0 + mw + lr + 8) * Nn;

    for (int t = 0; t < 16; t++) {
        const int jt = ((t << 1) + gid) << 6;
        const int buf = t & 1;
        CP_WAIT(0);
        GBAR(gid + 1);

        {
            const bf16* pv = Vh + (size_t)(jt + qr) * Dd + ghead;
            cpa16(uVh + soff0, pv);
            cpa16(uVh + soff0 + 16, pv + 8);
            const bf16* pv2 = Vl + (size_t)(jt + qr) * Dd + ghead;
            cpa16(uVl + soff0, pv2);
            cpa16(uVl + soff0 + 16, pv2 + 8);
        }
        CP_COMMIT();
        if (t + 1 < 16) {
            const bf16* pk = Kh + (size_t)(jt + 128 + qr) * Dd + ghead;
            cpa16(uKh[buf ^ 1] + soff0, pk);
            cpa16(uKh[buf ^ 1] + soff0 + 16, pk + 8);
            const bf16* pk2 = Kl + (size_t)(jt + 128 + qr) * Dd + ghead;
            cpa16(uKl[buf ^ 1] + soff0, pk2);
            cpa16(uKl[buf ^ 1] + soff0 + 16, pk2 + 8);
        }
        CP_COMMIT();

        unsigned short eu0[8], eu1[8];
#pragma unroll
        for (int nf = 0; nf < 8; nf++) {
            eu0[nf] = *(const unsigned short*)&E8[r0e + jt + (nf << 3) + lc];
            eu1[nf] = *(const unsigned short*)&E8[r1e + jt + (nf << 3) + lc];
        }

        // ---- S = Qh·(Kh+Kl) (2-term, R14-validated) ----
        float sf[8][4];
#pragma unroll
        for (int nf = 0; nf < 8; nf++)
#pragma unroll
            for (int cc = 0; cc < 4; cc++) sf[nf][cc] = 0.f;
#pragma unroll
        for (int ks = 0; ks < 2; ks++) {
            const int kk = ks << 4;
            uint32_t aqh[4];
            uint32_t offa = (uint32_t)(((mw + a_r) * 40 + kk + a_k) << 1);
            ldsm4(aqh[0], aqh[1], aqh[2], aqh[3], uQh + offa);
#pragma unroll
            for (int g = 0; g < 4; g++) {
                uint32_t bkh[4], bkl[4];
                uint32_t offb = (uint32_t)((((g << 4) + b_n) * 40 + kk + b_k) << 1);
                ldsm4(bkh[0], bkh[1], bkh[2], bkh[3], uKh[buf] + offb);
                ldsm4(bkl[0], bkl[1], bkl[2], bkl[3], uKl[buf] + offb);
#pragma unroll
                for (int sub = 0; sub < 2; sub++) {
                    int nf = (g << 1) + sub;
                    mma_bf16(sf[nf], aqh, &bkh[sub << 1]);
                    mma_bf16(sf[nf], aqh, &bkl[sub << 1]);
                }
            }
        }

        float mx0 = -1e30f, mx1 = -1e30f;
#pragma unroll
        for (int nf = 0; nf < 8; nf++) {
            sf[nf][0] = fmaf(sf[nf][0], scale2, s_eb[eu0[nf] & 0xffu]);
            sf[nf][1] = fmaf(sf[nf][1], scale2, s_eb[eu0[nf] >> 8]);
            sf[nf][2] = fmaf(sf[nf][2], scale2, s_eb[eu1[nf] & 0xffu]);
            sf[nf][3] = fmaf(sf[nf][3], scale2, s_eb[eu1[nf] >> 8]);
            mx0 = fmaxf(mx0, fmaxf(sf[nf][0], sf[nf][1]));
            mx1 = fmaxf(mx1, fmaxf(sf[nf][2], sf[nf][3]));
        }
        mx0 = fmaxf(mx0, __shfl_xor_sync(0xffffffffu, mx0, 1));
        mx0 = fmaxf(mx0, __shfl_xor_sync(0xffffffffu, mx0, 2));
        mx1 = fmaxf(mx1, __shfl_xor_sync(0xffffffffu, mx1, 1));
        mx1 = fmaxf(mx1, __shfl_xor_sync(0xffffffffu, mx1, 2));
        float mn0 = fmaxf(m0, mx0), mn1 = fmaxf(m1, mx1);
        float al0 = ex2f(m0 - mn0), al1 = ex2f(m1 - mn1);
        m0 = mn0;
        m1 = mn1;
#pragma unroll
        for (int nf = 0; nf < 4; nf++) {
            of[nf][0] *= al0;
            of[nf][1] *= al0;
            of[nf][2] *= al1;
            of[nf][3] *= al1;
        }

        float ps0 = 0.f, ps1 = 0.f;
        uint32_t aph[4][4];
#pragma unroll
        for (int nf = 0; nf < 8; nf++) {
            float p0 = ex2f(sf[nf][0] - mn0);
            float p1 = ex2f(sf[nf][1] - mn0);
            float p2 = ex2f(sf[nf][2] - mn1);
            float p3 = ex2f(sf[nf][3] - mn1);
            ps0 += p0 + p1;
            ps1 += p2 + p3;
            int ks = nf >> 1, base = (nf & 1) << 1;
            aph[ks][base + 0] = pack2bf(p0, p1);
            aph[ks][base + 1] = pack2bf(p2, p3);
        }
        ps0 += __shfl_xor_sync(0xffffffffu, ps0, 1);
        ps0 += __shfl_xor_sync(0xffffffffu, ps0, 2);
        ps1 += __shfl_xor_sync(0xffffffffu, ps1, 1);
        ps1 += __shfl_xor_sync(0xffffffffu, ps1, 2);
        l0 = l0 * al0 + ps0;
        l1 = l1 * al1 + ps1;

        CP_WAIT(1);
        GBAR(gid + 1);
#pragma unroll
        for (int ks = 0; ks < 4; ks++) {
            const int kk = ks << 4;
#pragma unroll
            for (int dg = 0; dg < 2; dg++) {
                uint32_t bvh[4], bvl[4];
                uint32_t offv = (uint32_t)(((kk + a_r) * 40 + (dg << 4) + a_k) << 1);
                ldsm4t(bvh[0], bvh[1], bvh[2], bvh[3], uVh + offv);
                ldsm4t(bvl[0], bvl[1], bvl[2], bvl[3], uVl + offv);
#pragma unroll
                for (int sub = 0; sub < 2; sub++) {
                    int nf = (dg << 1) + sub;
                    mma_bf16(of[nf], aph[ks], &bvh[sub << 1]);
                    mma_bf16(of[nf], aph[ks], &bvl[sub << 1]);
                }
            }
        }
    }

    // ---- split-softmax merge ----
    CP_WAIT(0);
    __syncthreads();
    float* mg = (float*)dsm;
    float* lg = mg + 256;
    float* og = lg + 256;
    if (gid == 1) {
        mg[gt * 2] = m0;
        mg[gt * 2 + 1] = m1;
        lg[gt * 2] = l0;
        lg[gt * 2 + 1] = l1;
#pragma unroll
        for (int nf = 0; nf < 4; nf++)
#pragma unroll
            for (int c = 0; c < 4; c++) og[gt * 16 + nf * 4 + c] = of[nf][c];
    }
    __syncthreads();
    if (gid == 0) {
        float mb0 = mg[gt * 2], mb1 = mg[gt * 2 + 1];
        float lb0 = lg[gt * 2], lb1 = lg[gt * 2 + 1];
        float mn0 = fmaxf(m0, mb0), mn1 = fmaxf(m1, mb1);
        float a0 = ex2f(m0 - mn0), bb0 = ex2f(mb0 - mn0);
        float a1 = ex2f(m1 - mn1), bb1 = ex2f(mb1 - mn1);
        float inv0 = 1.0f / (l0 * a0 + lb0 * bb0);
        float inv1 = 1.0f / (l1 * a1 + lb1 * bb1);
        int row0 = i0 + mw + lr, row1 = row0 + 8;
#pragma unroll
        for (int nf = 0; nf < 4; nf++) {
            int col = h * DKk + (nf << 3) + lc;
            float v0 = (of[nf][0] * a0 + og[gt * 16 + nf * 4 + 0] * bb0) * inv0;
            float v1 = (of[nf][1] * a0 + og[gt * 16 + nf * 4 + 1] * bb0) * inv0;
            float v2 = (of[nf][2] * a1 + og[gt * 16 + nf * 4 + 2] * bb1) * inv1;
            float v3 = (of[nf][3] * a1 + og[gt * 16 + nf * 4 + 3] * bb1) * inv1;
            float h0 = __bfloat162float(__float2bfloat16(v0));
            float h1 = __bfloat162float(__float2bfloat16(v1));
            float h2 = __bfloat162float(__float2bfloat16(v2));
            float h3 = __bfloat162float(__float2bfloat16(v3));
            *(uint32_t*)&Oh[(size_t)row0 * Dd + col] = pack2bf(h0, h1);
            *(uint32_t*)&Oh[(size_t)row1 * Dd + col] = pack2bf(h2, h3);
            *(uint32_t*)&Ol[(size_t)row0 * Dd + col] = pack2bf(v0 - h0, v1 - h1);
            *(uint32_t*)&Ol[(size_t)row1 * Dd + col] = pack2bf(v2 - h2, v3 - h3);
        }
    }
}

// ---------------- reduce + bias + residual + LayerNorm (R13 256-thr shuffle) ----------------
template <int S>
__global__ void addln_red_kernel(float* __restrict__ x, const float* __restrict__ part,
                                 const float* __restrict__ bias, const float* __restrict__ g,
                                 const float* __restrict__ b, bf16* __restrict__ xh,
                                 bf16* __restrict__ xl) {
    int i = blockIdx.x, d = threadIdx.x;
    int lane = d & 31, w = d >> 5;
    __shared__ float ws[8];
    float v = x[i * Dd + d] + bias[d];
#pragma unroll
    for (int s = 0; s < S; s++) v += part[(size_t)s * Nn * Dd + (size_t)i * Dd + d];
    float t = v;
#pragma unroll
    for (int off = 16; off > 0; off >>= 1) t += __shfl_xor_sync(0xffffffffu, t, off);
    if (lane == 0) ws[w] = t;
    __syncthreads();
    float mean = (ws[0] + ws[1] + ws[2] + ws[3] + ws[4] + ws[5] + ws[6] + ws[7]) * (1.0f / Dd);
    float dv = v - mean;
    t = dv * dv;
#pragma unroll
    for (int off = 16; off > 0; off >>= 1) t += __shfl_xor_sync(0xffffffffu, t, off);
    __syncthreads();
    if (lane == 0) ws[w] = t;
    __syncthreads();
    float var = (ws[0] + ws[1] + ws[2] + ws[3] + ws[4] + ws[5] + ws[6] + ws[7]) * (1.0f / Dd);
    float outv = dv * rsqrtf(var + 1e-5f) * g[d] + b[d];
    x[i * Dd + d] = outv;
    bf16 h = __float2bfloat16(outv);
    xh[i * Dd + d] = h;
    xl[i * Dd + d] = __float2bfloat16(outv - __bfloat162float(h));
}

__global__ void pool_kernel(const float* __restrict__ x, float* __restrict__ p) {
    int j = blockIdx.x * 32 + threadIdx.x;
    int yy = threadIdx.y;
    float s = 0.f, mx = -1e30f;
    for (int i = yy; i < Nn; i += 8) {
        float v = x[(size_t)i * Dd + j];
        s += v;
        mx = fmaxf(mx, v);
    }
    __shared__ float ss[8][33], sm[8][33];
    ss[yy][threadIdx.x] = s;
    sm[yy][threadIdx.x] = mx;
    __syncthreads();
    if (yy == 0) {
        for (int k2 = 1; k2 < 8; k2++) {
            s += ss[k2][threadIdx.x];
            mx = fmaxf(mx, sm[k2][threadIdx.x]);
        }
        p[j] = s * (1.0f / Nn);
        p[Dd + j] = mx;
    }
}

__global__ void head_kernel(const float* __restrict__ pooled, const float* __restrict__ Wr,
                            const float* __restrict__ br, float* __restrict__ out) {
    __shared__ float sp[2 * Dd];
    int d = threadIdx.x;
    sp[d] = pooled[d];
    sp[d + Dd] = pooled[d + Dd];
    __syncthreads();
    float acc = br[d];
#pragma unroll 8
    for (int k2 = 0; k2 < 2 * Dd; k2++) acc = fmaf(sp[k2], Wr[(size_t)k2 * Dd + d], acc);
    out[d] = acc;
}

// ---------------- host launcher ----------------
extern "C" void kernel_launch(void* const* d_in, const int* in_sizes, int n_in,
                              void* d_out, int out_size) {
    const int* node_types = (const int*)d_in[0];
    const int* edge_idx = (const int*)d_in[1];
    const float* node_emb = (const float*)d_in[2];
    const float* Wq = (const float*)d_in[3];
    const float* Wk = (const float*)d_in[4];
    const float* Wv = (const float*)d_in[5];
    const float* Wo = (const float*)d_in[6];
    const float* bo = (const float*)d_in[7];
    const float* eb = (const float*)d_in[8];
    const float* W1 = (const float*)d_in[9];
    const float* b1 = (const float*)d_in[10];
    const float* W2 = (const float*)d_in[11];
    const float* b2 = (const float*)d_in[12];
    const float* ln1g = (const float*)d_in[13];
    const float* ln1b = (const float*)d_in[14];
    const float* ln2g = (const float*)d_in[15];
    const float* ln2b = (const float*)d_in[16];
    const float* Wr = (const float*)d_in[17];
    const float* brr = (const float*)d_in[18];
    float* out = (float*)d_out;

    float *x, *part, *pool;
    unsigned char* e8;
    bf16 *xh, *xl, *qh, *ql, *kh, *kl, *vh, *vl, *atth, *attl, *t1h, *t1l;
    bf16 *wqh, *wql, *wkh, *wkl, *wvh, *wvl, *woh, *wol, *w1h, *w1l, *w2h, *w2l;
    cudaGetSymbolAddress((void**)&x, g_x);
    cudaGetSymbolAddress((void**)&part, g_part);
    cudaGetSymbolAddress((void**)&pool, g_pool);
    cudaGetSymbolAddress((void**)&e8, g_e8);
    cudaGetSymbolAddress((void**)&xh, g_xh);
    cudaGetSymbolAddress((void**)&xl, g_xl);
    cudaGetSymbolAddress((void**)&qh, g_qh);
    cudaGetSymbolAddress((void**)&ql, g_ql);
    cudaGetSymbolAddress((void**)&kh, g_kh);
    cudaGetSymbolAddress((void**)&kl, g_kl);
    cudaGetSymbolAddress((void**)&vh, g_vh);
    cudaGetSymbolAddress((void**)&vl, g_vl);
    cudaGetSymbolAddress((void**)&atth, g_atth);
    cudaGetSymbolAddress((void**)&attl, g_attl);
    cudaGetSymbolAddress((void**)&t1h, g_t1h);
    cudaGetSymbolAddress((void**)&t1l, g_t1l);
    cudaGetSymbolAddress((void**)&wqh, g_wqh);
    cudaGetSymbolAddress((void**)&wql, g_wql);
    cudaGetSymbolAddress((void**)&wkh, g_wkh);
    cudaGetSymbolAddress((void**)&wkl, g_wkl);
    cudaGetSymbolAddress((void**)&wvh, g_wvh);
    cudaGetSymbolAddress((void**)&wvl, g_wvl);
    cudaGetSymbolAddress((void**)&woh, g_woh);
    cudaGetSymbolAddress((void**)&wol, g_wol);
    cudaGetSymbolAddress((void**)&w1h, g_w1h);
    cudaGetSymbolAddress((void**)&w1l, g_w1l);
    cudaGetSymbolAddress((void**)&w2h, g_w2h);
    cudaGetSymbolAddress((void**)&w2l, g_w2l);

    cudaFuncSetAttribute(attn_hmma_kernel, cudaFuncAttributeMaxDynamicSharedMemorySize,
                         ATTN_SMEM);
    cudaFuncSetAttribute(hmma_qkv_kernel, cudaFuncAttributeMaxDynamicSharedMemorySize,
                         GEMM_SMEM);
    cudaFuncSetAttribute(hmma_gemm_kernel<0, 2, 0>, cudaFuncAttributeMaxDynamicSharedMemorySize,
                         GEMM_SMEM);
    cudaFuncSetAttribute(hmma_gemm_kernel<1, 1, 1>, cudaFuncAttributeMaxDynamicSharedMemorySize,
                         GEMM_SMEM);

    embed_kernel<<<Nn, Dd>>>(node_types, node_emb, x, xh, xl);
    cvt_e8_kernel<<<(Nn * Nn / 4) / 256, 256>>>(edge_idx, e8);

    wsplit4_kernel<<<dim3(8, 8, 4 * Ll), dim3(32, 8)>>>(Wq, Wk, Wv, Wo, wqh, wql, wkh, wkl,
                                                        wvh, wvl, woh, wol);
    wsplit_kernel<<<dim3(32, 8, Ll), dim3(32, 8)>>>(W1, w1h, w1l, Dd, DFFf);
    wsplit_kernel<<<dim3(8, 32, Ll), dim3(32, 8)>>>(W2, w2h, w2l, DFFf, Dd);

    for (int l = 0; l < Ll; l++) {
        size_t wo256 = (size_t)l * Dd * Dd;
        size_t woff1 = (size_t)l * Dd * DFFf;
        hmma_qkv_kernel<<<dim3(4, 16, 3), 256, GEMM_SMEM>>>(
            xh, xl, wqh + wo256, wql + wo256, wkh + wo256, wkl + wo256, wvh + wo256,
            wvl + wo256, qh, ql, kh, kl, vh, vl);

        attn_hmma_kernel<<<dim3(Nn / 64, Hh), 256, ATTN_SMEM>>>(
            qh, ql, kh, kl, vh, vl, e8, eb + l * NEDGEe * Hh, atth, attl);

        hmma_gemm_kernel<0, 2, 0><<<dim3(4, 16, 2), 256, GEMM_SMEM>>>(
            atth, attl, woh + wo256, wol + wo256, nullptr, part, nullptr, nullptr, Dd, Dd);
        addln_red_kernel<2><<<Nn, Dd>>>(x, part, bo + l * Dd, ln1g + l * Dd, ln1b + l * Dd, xh,
                                        xl);

        hmma_gemm_kernel<1, 1, 1><<<dim3(16, 16, 1), 256, GEMM_SMEM>>>(
            xh, xl, w1h + woff1, w1l + woff1, b1 + l * DFFf, nullptr, t1h, t1l, Dd, DFFf);

        hmma_gemm_kernel<0, 2, 0><<<dim3(4, 16, 2), 256, GEMM_SMEM>>>(
            t1h, t1l, w2h + woff1, w2l + woff1, nullptr, part, nullptr, nullptr, DFFf, Dd);
        addln_red_kernel<2><<<Nn, Dd>>>(x, part, b2 + l * Dd, ln2g + l * Dd, ln2b + l * Dd, xh,
                                        xl);
    }

    pool_kernel<<<Dd / 32, dim3(32, 8)>>>(x, pool);
    head_kernel<<<1, Dd>>>(pool, Wr, brr, out);
}

// round 17
// speedup vs baseline: 1.0820x; 1.0566x over previous
#include <cuda_runtime.h>
#include <cuda_bf16.h>
#include <stdint.h>
#include <math.h>

#define Nn 2048
#define Dd 256
#define Hh 8
#define DKk 32
#define Ll 4
#define DFFf 1024
#define NEDGEe 5

typedef __nv_bfloat16 bf16;

// ---------------- portable MMA helpers (validated R8-R16) ----------------
__device__ __forceinline__ uint32_t smem_u32(const void* p) {
    uint32_t a;
    asm("{ .reg .u64 t; cvta.to.shared.u64 t, %1; cvt.u32.u64 %0, t; }" : "=r"(a) : "l"(p));
    return a;
}
__device__ __forceinline__ void ldsm4(uint32_t& r0, uint32_t& r1, uint32_t& r2, uint32_t& r3,
                                      uint32_t addr) {
    asm volatile("ldmatrix.sync.aligned.m8n8.x4.shared.b16 {%0,%1,%2,%3}, [%4];"
                 : "=r"(r0), "=r"(r1), "=r"(r2), "=r"(r3)
                 : "r"(addr));
}
__device__ __forceinline__ void ldsm4t(uint32_t& r0, uint32_t& r1, uint32_t& r2, uint32_t& r3,
                                       uint32_t addr) {
    asm volatile("ldmatrix.sync.aligned.m8n8.x4.trans.shared.b16 {%0,%1,%2,%3}, [%4];"
                 : "=r"(r0), "=r"(r1), "=r"(r2), "=r"(r3)
                 : "r"(addr));
}
__device__ __forceinline__ void mma_bf16(float* d, const uint32_t* a, const uint32_t* b) {
    asm volatile(
        "mma.sync.aligned.m16n8k16.row.col.f32.bf16.bf16.f32 "
        "{%0,%1,%2,%3}, {%4,%5,%6,%7}, {%8,%9}, {%0,%1,%2,%3};"
        : "+f"(d[0]), "+f"(d[1]), "+f"(d[2]), "+f"(d[3])
        : "r"(a[0]), "r"(a[1]), "r"(a[2]), "r"(a[3]), "r"(b[0]), "r"(b[1]));
}
__device__ __forceinline__ uint32_t pack2bf(float a, float b) {
    uint32_t r;
    asm("cvt.rn.bf16x2.f32 %0, %1, %2;" : "=r"(r) : "f"(b), "f"(a));
    return r;
}
__device__ __forceinline__ float ex2f(float x) {
    float y;
    asm("ex2.approx.f32 %0, %1;" : "=f"(y) : "f"(x));
    return y;
}
__device__ __forceinline__ void cpa16(uint32_t dst, const void* src) {
    asm volatile("cp.async.cg.shared.global [%0], [%1], 16;" :: "r"(dst), "l"(src));
}
#define CP_COMMIT() asm volatile("cp.async.commit_group;" ::: "memory")
#define CP_WAIT(n) asm volatile("cp.async.wait_group %0;" :: "n"(n) : "memory")
#define GBAR(id) asm volatile("bar.sync %0, %1;" :: "r"(id), "r"(128) : "memory")

// ---------------- scratch ----------------
__device__ float g_x[Nn * Dd];
__device__ float g_part[2 * Nn * Dd];
__device__ unsigned char g_e8[Nn * Nn];
__device__ float g_pool[2 * Dd];
__device__ bf16 g_xh[Nn * Dd], g_xl[Nn * Dd];
__device__ bf16 g_qh[Nn * Dd], g_ql[Nn * Dd];
__device__ bf16 g_kh[Nn * Dd], g_kl[Nn * Dd];
__device__ bf16 g_vh[Nn * Dd], g_vl[Nn * Dd];
__device__ bf16 g_atth[Nn * Dd], g_attl[Nn * Dd];
__device__ bf16 g_t1h[Nn * DFFf], g_t1l[Nn * DFFf];
__device__ bf16 g_wqh[Ll * Dd * Dd], g_wql[Ll * Dd * Dd];
__device__ bf16 g_wkh[Ll * Dd * Dd], g_wkl[Ll * Dd * Dd];
__device__ bf16 g_wvh[Ll * Dd * Dd], g_wvl[Ll * Dd * Dd];
__device__ bf16 g_woh[Ll * Dd * Dd], g_wol[Ll * Dd * Dd];
__device__ bf16 g_w1h[Ll * Dd * DFFf], g_w1l[Ll * Dd * DFFf];
__device__ bf16 g_w2h[Ll * DFFf * Dd], g_w2l[Ll * DFFf * Dd];

// ---------------- embedding gather (+split) ----------------
__global__ void embed_kernel(const int* __restrict__ nt, const float* __restrict__ emb,
                             float* __restrict__ x, bf16* __restrict__ xh, bf16* __restrict__ xl) {
    int i = blockIdx.x;
    int d = threadIdx.x;
    float v = emb[nt[i] * Dd + d];
    x[i * Dd + d] = v;
    bf16 h = __float2bfloat16(v);
    xh[i * Dd + d] = h;
    xl[i * Dd + d] = __float2bfloat16(v - __bfloat162float(h));
}

__global__ void cvt_e8_kernel(const int* __restrict__ e, unsigned char* __restrict__ o) {
    int i = blockIdx.x * blockDim.x + threadIdx.x;
    int4 v = ((const int4*)e)[i];
    uchar4 u;
    u.x = (unsigned char)v.x; u.y = (unsigned char)v.y;
    u.z = (unsigned char)v.z; u.w = (unsigned char)v.w;
    ((uchar4*)o)[i] = u;
}

// ---------------- weight transpose + split ----------------
__device__ __forceinline__ void wsplit_body(const float* __restrict__ Wl, bf16* __restrict__ Thl,
                                            bf16* __restrict__ Tll, int Kd, int Nc) {
    __shared__ float sh[32][33], slo[32][33];
    int n0 = blockIdx.x << 5, k0 = blockIdx.y << 5;
    int tx = threadIdx.x, ty = threadIdx.y;
#pragma unroll
    for (int r = 0; r < 4; r++) {
        int kk = ty + (r << 3);
        float v = Wl[(size_t)(k0 + kk) * Nc + n0 + tx];
        float h = __bfloat162float(__float2bfloat16(v));
        sh[kk][tx] = h;
        slo[kk][tx] = v - h;
    }
    __syncthreads();
#pragma unroll
    for (int r = 0; r < 4; r++) {
        int nn = ty + (r << 3);
        Thl[(size_t)(n0 + nn) * Kd + k0 + tx] = __float2bfloat16(sh[tx][nn]);
        Tll[(size_t)(n0 + nn) * Kd + k0 + tx] = __float2bfloat16(slo[tx][nn]);
    }
}

__global__ void wsplit_kernel(const float* __restrict__ W, bf16* __restrict__ Th,
                              bf16* __restrict__ Tl, int Kd, int Nc) {
    wsplit_body(W + (size_t)blockIdx.z * Kd * Nc, Th + (size_t)blockIdx.z * Kd * Nc,
                Tl + (size_t)blockIdx.z * Kd * Nc, Kd, Nc);
}

__global__ void wsplit4_kernel(const float* __restrict__ Wq, const float* __restrict__ Wk,
                               const float* __restrict__ Wv, const float* __restrict__ Wo,
                               bf16* __restrict__ qh, bf16* __restrict__ ql,
                               bf16* __restrict__ kh, bf16* __restrict__ kl,
                               bf16* __restrict__ vh, bf16* __restrict__ vl,
                               bf16* __restrict__ oh, bf16* __restrict__ ol) {
    int l = blockIdx.z >> 2, w = blockIdx.z & 3;
    size_t off = (size_t)l * Dd * Dd;
    const float* W = (w == 0) ? Wq : (w == 1) ? Wk : (w == 2) ? Wv : Wo;
    bf16* Th = (w == 0) ? qh : (w == 1) ? kh : (w == 2) ? vh : oh;
    bf16* Tl = (w == 0) ? ql : (w == 1) ? kl : (w == 2) ? vl : ol;
    wsplit_body(W + off, Th + off, Tl + off, Dd, Dd);
}

// ---------------- split-bf16 HMMA GEMM, cp.async 2-stage pipeline (R13) ----------------
// OSPLIT==2 with Cl==nullptr skips the lo store (hi-only output).
#define GEMM_SMEM 61440
template <int ACT, int OSPLIT>
__device__ __forceinline__ void hmma_gemm_body(
    const bf16* __restrict__ Ah, const bf16* __restrict__ Al,
    const bf16* __restrict__ Bh, const bf16* __restrict__ Bl,
    const float* __restrict__ bias, float* __restrict__ Cf,
    bf16* __restrict__ Ch, bf16* __restrict__ Cl,
    int Kd, int kbeg, int kslice, int Nc) {
    extern __shared__ bf16 gsm[];
    const int tid = threadIdx.x;
    const int wid = tid >> 5, lane = tid & 31;
    const int i0 = blockIdx.y << 7, j0 = blockIdx.x << 6;
    const int mw = (wid & 3) << 5;
    const int nw = (wid >> 2) << 5;

    float acc[2][4][4];
#pragma unroll
    for (int a = 0; a < 2; a++)
#pragma unroll
        for (int b = 0; b < 4; b++)
#pragma unroll
            for (int cc = 0; cc < 4; cc++) acc[a][b][cc] = 0.f;

    const int a_r = lane & 15;
    const int a_k = (lane >> 4) << 3;
    const int b_n = (lane & 7) + ((lane & 16) >> 1);
    const int b_k = lane & 8;

    uint32_t uAh[2] = {smem_u32(gsm), smem_u32(gsm + 5120)};
    uint32_t uAl[2] = {smem_u32(gsm + 10240), smem_u32(gsm + 15360)};
    uint32_t uBh[2] = {smem_u32(gsm + 20480), smem_u32(gsm + 23040)};
    uint32_t uBl[2] = {smem_u32(gsm + 25600), smem_u32(gsm + 28160)};

    const int r = tid >> 1, hf = (tid & 1) << 4;
    const int tb = tid & 127;
    const int rb = tb >> 1, hb = (tb & 1) << 4;
    const bf16* Bsel = (tid < 128) ? Bh : Bl;
    const uint32_t aoff = (uint32_t)((r * 40 + hf) << 1);
    const uint32_t boff = (uint32_t)((rb * 40 + hb) << 1);

    {
        const bf16* pAh = Ah + (size_t)(i0 + r) * Kd + kbeg + hf;
        const bf16* pAl = Al + (size_t)(i0 + r) * Kd + kbeg + hf;
        cpa16(uAh[0] + aoff, pAh);
        cpa16(uAh[0] + aoff + 16, pAh + 8);
        cpa16(uAl[0] + aoff, pAl);
        cpa16(uAl[0] + aoff + 16, pAl + 8);
        const bf16* pB = Bsel + (size_t)(j0 + rb) * Kd + kbeg + hb;
        uint32_t ub = (tid < 128) ? uBh[0] : uBl[0];
        cpa16(ub + boff, pB);
        cpa16(ub + boff + 16, pB + 8);
    }
    CP_COMMIT();

    const int nch = kslice >> 5;
    for (int c = 0; c < nch; c++) {
        const int buf = c & 1;
        CP_WAIT(0);
        __syncthreads();

        if (c + 1 < nch) {
            int kt = kbeg + ((c + 1) << 5);
            int nb = buf ^ 1;
            const bf16* pAh = Ah + (size_t)(i0 + r) * Kd + kt + hf;
            const bf16* pAl = Al + (size_t)(i0 + r) * Kd + kt + hf;
            cpa16(uAh[nb] + aoff, pAh);
            cpa16(uAh[nb] + aoff + 16, pAh + 8);
            cpa16(uAl[nb] + aoff, pAl);
            cpa16(uAl[nb] + aoff + 16, pAl + 8);
            const bf16* pB = Bsel + (size_t)(j0 + rb) * Kd + kt + hb;
            uint32_t ub = (tid < 128) ? uBh[nb] : uBl[nb];
            cpa16(ub + boff, pB);
            cpa16(ub + boff + 16, pB + 8);
        }
        CP_COMMIT();

#pragma unroll
        for (int ks = 0; ks < 2; ks++) {
            const int kk = ks << 4;
            uint32_t ah[2][4], al[2][4], bhf[2][4], blf[2][4];
#pragma unroll
            for (int mf = 0; mf < 2; mf++) {
                uint32_t off = (uint32_t)(((mw + (mf << 4) + a_r) * 40 + kk + a_k) << 1);
                ldsm4(ah[mf][0], ah[mf][1], ah[mf][2], ah[mf][3], uAh[buf] + off);
                ldsm4(al[mf][0], al[mf][1], al[mf][2], al[mf][3], uAl[buf] + off);
            }
#pragma unroll
            for (int g = 0; g < 2; g++) {
                uint32_t off = (uint32_t)(((nw + (g << 4) + b_n) * 40 + kk + b_k) << 1);
                ldsm4(bhf[g][0], bhf[g][1], bhf[g][2], bhf[g][3], uBh[buf] + off);
                ldsm4(blf[g][0], blf[g][1], blf[g][2], blf[g][3], uBl[buf] + off);
            }
#pragma unroll
            for (int mf = 0; mf < 2; mf++)
#pragma unroll
                for (int nf = 0; nf < 4; nf++) {
                    const uint32_t* ph = &bhf[nf >> 1][(nf & 1) << 1];
                    const uint32_t* pl = &blf[nf >> 1][(nf & 1) << 1];
                    mma_bf16(acc[mf][nf], ah[mf], ph);
                    mma_bf16(acc[mf][nf], ah[mf], pl);
                    mma_bf16(acc[mf][nf], al[mf], ph);
                }
        }
    }

    const int lr = lane >> 2, lc = (lane & 3) << 1;
#pragma unroll
    for (int mf = 0; mf < 2; mf++)
#pragma unroll
        for (int rp = 0; rp < 2; rp++) {
            int row = i0 + mw + (mf << 4) + lr + (rp << 3);
#pragma unroll
            for (int nf = 0; nf < 4; nf++) {
                float v0 = acc[mf][nf][(rp << 1) + 0];
                float v1 = acc[mf][nf][(rp << 1) + 1];
                int col = j0 + nw + (nf << 3) + lc;
                if (OSPLIT == 0) {
                    if (bias) {
                        v0 += bias[col];
                        v1 += bias[col + 1];
                    }
                    *(float2*)&Cf[(size_t)row * Nc + col] = make_float2(v0, v1);
                } else {
                    if (OSPLIT == 1) {
                        v0 += bias[col];
                        v1 += bias[col + 1];
                        if (ACT == 1) {
                            v0 = 0.5f * v0 * (1.0f + erff(v0 * 0.70710678118654752f));
                            v1 = 0.5f * v1 * (1.0f + erff(v1 * 0.70710678118654752f));
                        }
                    }
                    bf16 h0 = __float2bfloat16(v0), h1 = __float2bfloat16(v1);
                    Ch[(size_t)row * Nc + col] = h0;
                    Ch[(size_t)row * Nc + col + 1] = h1;
                    if (OSPLIT == 1 || Cl != nullptr) {
                        Cl[(size_t)row * Nc + col] = __float2bfloat16(v0 - __bfloat162float(h0));
                        Cl[(size_t)row * Nc + col + 1] =
                            __float2bfloat16(v1 - __bfloat162float(h1));
                    }
                }
            }
        }
}

template <int ACT, int SPLIT, int OSPLIT>
__global__ void __launch_bounds__(256) hmma_gemm_kernel(
    const bf16* __restrict__ Ah, const bf16* __restrict__ Al,
    const bf16* __restrict__ Bh, const bf16* __restrict__ Bl,
    const float* __restrict__ bias, float* __restrict__ Cf,
    bf16* __restrict__ Ch, bf16* __restrict__ Cl, int Kd, int Nc) {
    int kslice = Kd / SPLIT;
    int kbeg = blockIdx.z * kslice;
    float* Cz = (SPLIT > 1) ? Cf + (size_t)blockIdx.z * Nn * Nc : Cf;
    hmma_gemm_body<ACT, OSPLIT>(Ah, Al, Bh, Bl, SPLIT > 1 ? nullptr : bias, Cz, Ch, Cl,
                                Kd, kbeg, kslice, Nc);
}

// QKV: q gets hi-only output (attention never reads Ql)
__global__ void __launch_bounds__(256) hmma_qkv_kernel(
    const bf16* __restrict__ Ah, const bf16* __restrict__ Al,
    const bf16* __restrict__ Bh0, const bf16* __restrict__ Bl0,
    const bf16* __restrict__ Bh1, const bf16* __restrict__ Bl1,
    const bf16* __restrict__ Bh2, const bf16* __restrict__ Bl2,
    bf16* __restrict__ qh, bf16* __restrict__ kh,
    bf16* __restrict__ kl, bf16* __restrict__ vh, bf16* __restrict__ vl) {
    int z = blockIdx.z;
    const bf16* Bh = (z == 0) ? Bh0 : (z == 1) ? Bh1 : Bh2;
    const bf16* Bl = (z == 0) ? Bl0 : (z == 1) ? Bl1 : Bl2;
    bf16* Ch = (z == 0) ? qh : (z == 1) ? kh : vh;
    bf16* Cl = (z == 0) ? nullptr : (z == 1) ? kl : vl;
    hmma_gemm_body<0, 2>(Ah, Al, Bh, Bl, nullptr, nullptr, Ch, Cl, Dd, 0, Dd, Dd);
}

// ---------------- HMMA flash attention: 2-term S, hi-only V ----------------
// smem (bf16 el): Qh @0 (2560); Kh @2560+(gid*2+b)*2560 (10240); Kl @12800 (10240);
// Vh @23040+gid*2560 (5120). Total 28160 el = 56320 B.
#define ATTN_SMEM 56320
__global__ void __launch_bounds__(256) attn_hmma_kernel(
    const bf16* __restrict__ Qh,
    const bf16* __restrict__ Kh, const bf16* __restrict__ Kl,
    const bf16* __restrict__ Vh,
    const unsigned char* __restrict__ E8, const float* __restrict__ ebl,
    bf16* __restrict__ Oh, bf16* __restrict__ Ol) {
    extern __shared__ bf16 dsm[];
    __shared__ float s_eb[8];

    const int h = blockIdx.y;
    const int i0 = blockIdx.x << 6;
    const int tid = threadIdx.x;
    const int wid = tid >> 5, lane = tid & 31;
    const int gid = wid >> 2;
    const int mw = (wid & 3) << 4;
    const int gt = tid & 127;

    if (tid < NEDGEe) s_eb[tid] = ebl[tid * Hh + h] * 1.4426950408889634f;

    const int a_r = lane & 15, a_k = (lane >> 4) << 3;
    const int b_n = (lane & 7) + ((lane & 16) >> 1), b_k = lane & 8;
    const int lr = lane >> 2, lc = (lane & 3) << 1;

    const uint32_t uQh = smem_u32(dsm);
    uint32_t uKh[2], uKl[2];
    uKh[0] = smem_u32(dsm + 2560 + (gid * 2) * 2560);
    uKh[1] = smem_u32(dsm + 2560 + (gid * 2 + 1) * 2560);
    uKl[0] = smem_u32(dsm + 12800 + (gid * 2) * 2560);
    uKl[1] = smem_u32(dsm + 12800 + (gid * 2 + 1) * 2560);
    const uint32_t uVh = smem_u32(dsm + 23040 + gid * 2560);

    const int qr = gt >> 1, qh4 = (gt & 1) << 4;
    const uint32_t soff0 = (uint32_t)((qr * 40 + qh4) << 1);
    const size_t ghead = (size_t)h * DKk + qh4;

    {
        const bf16* pk = Kh + (size_t)(gid * 64 + qr) * Dd + ghead;
        cpa16(uKh[0] + soff0, pk);
        cpa16(uKh[0] + soff0 + 16, pk + 8);
        const bf16* pk2 = Kl + (size_t)(gid * 64 + qr) * Dd + ghead;
        cpa16(uKl[0] + soff0, pk2);
        cpa16(uKl[0] + soff0 + 16, pk2 + 8);
    }
    CP_COMMIT();
    if (gid == 0) {
        const bf16* p = Qh + (size_t)(i0 + qr) * Dd + ghead;
        *(uint4*)(dsm + qr * 40 + qh4) = *(const uint4*)p;
        *(uint4*)(dsm + qr * 40 + qh4 + 8) = *(const uint4*)(p + 8);
    }
    __syncthreads();

    float of[4][4];
#pragma unroll
    for (int a = 0; a < 4; a++)
#pragma unroll
        for (int b = 0; b < 4; b++) of[a][b] = 0.f;
    float m0 = -1e30f, m1 = -1e30f, l0 = 0.f, l1 = 0.f;
    const float scale2 = 0.17677669529663687f * 1.4426950408889634f;
    const size_t r0e = (size_t)(i0 + mw + lr) * Nn;
    const size_t r1e = (size_t)(i0 + mw + lr + 8) * Nn;

    for (int t = 0; t < 16; t++) {
        const int jt = ((t << 1) + gid) << 6;
        const int buf = t & 1;
        CP_WAIT(0);
        GBAR(gid + 1);

        {
            const bf16* pv = Vh + (size_t)(jt + qr) * Dd + ghead;
            cpa16(uVh + soff0, pv);
            cpa16(uVh + soff0 + 16, pv + 8);
        }
        CP_COMMIT();
        if (t + 1 < 16) {
            const bf16* pk = Kh + (size_t)(jt + 128 + qr) * Dd + ghead;
            cpa16(uKh[buf ^ 1] + soff0, pk);
            cpa16(uKh[buf ^ 1] + soff0 + 16, pk + 8);
            const bf16* pk2 = Kl + (size_t)(jt + 128 + qr) * Dd + ghead;
            cpa16(uKl[buf ^ 1] + soff0, pk2);
            cpa16(uKl[buf ^ 1] + soff0 + 16, pk2 + 8);
        }
        CP_COMMIT();

        unsigned short eu0[8], eu1[8];
#pragma unroll
        for (int nf = 0; nf < 8; nf++) {
            eu0[nf] = *(const unsigned short*)&E8[r0e + jt + (nf << 3) + lc];
            eu1[nf] = *(const unsigned short*)&E8[r1e + jt + (nf << 3) + lc];
        }

        // ---- S = Qh·(Kh+Kl) ----
        float sf[8][4];
#pragma unroll
        for (int nf = 0; nf < 8; nf++)
#pragma unroll
            for (int cc = 0; cc < 4; cc++) sf[nf][cc] = 0.f;
#pragma unroll
        for (int ks = 0; ks < 2; ks++) {
            const int kk = ks << 4;
            uint32_t aqh[4];
            uint32_t offa = (uint32_t)(((mw + a_r) * 40 + kk + a_k) << 1);
            ldsm4(aqh[0], aqh[1], aqh[2], aqh[3], uQh + offa);
#pragma unroll
            for (int g = 0; g < 4; g++) {
                uint32_t bkh[4], bkl[4];
                uint32_t offb = (uint32_t)((((g << 4) + b_n) * 40 + kk + b_k) << 1);
                ldsm4(bkh[0], bkh[1], bkh[2], bkh[3], uKh[buf] + offb);
                ldsm4(bkl[0], bkl[1], bkl[2], bkl[3], uKl[buf] + offb);
#pragma unroll
                for (int sub = 0; sub < 2; sub++) {
                    int nf = (g << 1) + sub;
                    mma_bf16(sf[nf], aqh, &bkh[sub << 1]);
                    mma_bf16(sf[nf], aqh, &bkl[sub << 1]);
                }
            }
        }

        float mx0 = -1e30f, mx1 = -1e30f;
#pragma unroll
        for (int nf = 0; nf < 8; nf++) {
            sf[nf][0] = fmaf(sf[nf][0], scale2, s_eb[eu0[nf] & 0xffu]);
            sf[nf][1] = fmaf(sf[nf][1], scale2, s_eb[eu0[nf] >> 8]);
            sf[nf][2] = fmaf(sf[nf][2], scale2, s_eb[eu1[nf] & 0xffu]);
            sf[nf][3] = fmaf(sf[nf][3], scale2, s_eb[eu1[nf] >> 8]);
            mx0 = fmaxf(mx0, fmaxf(sf[nf][0], sf[nf][1]));
            mx1 = fmaxf(mx1, fmaxf(sf[nf][2], sf[nf][3]));
        }
        mx0 = fmaxf(mx0, __shfl_xor_sync(0xffffffffu, mx0, 1));
        mx0 = fmaxf(mx0, __shfl_xor_sync(0xffffffffu, mx0, 2));
        mx1 = fmaxf(mx1, __shfl_xor_sync(0xffffffffu, mx1, 1));
        mx1 = fmaxf(mx1, __shfl_xor_sync(0xffffffffu, mx1, 2));
        float mn0 = fmaxf(m0, mx0), mn1 = fmaxf(m1, mx1);
        float al0 = ex2f(m0 - mn0), al1 = ex2f(m1 - mn1);
        m0 = mn0;
        m1 = mn1;
#pragma unroll
        for (int nf = 0; nf < 4; nf++) {
            of[nf][0] *= al0;
            of[nf][1] *= al0;
            of[nf][2] *= al1;
            of[nf][3] *= al1;
        }

        float ps0 = 0.f, ps1 = 0.f;
        uint32_t aph[4][4];
#pragma unroll
        for (int nf = 0; nf < 8; nf++) {
            float p0 = ex2f(sf[nf][0] - mn0);
            float p1 = ex2f(sf[nf][1] - mn0);
            float p2 = ex2f(sf[nf][2] - mn1);
            float p3 = ex2f(sf[nf][3] - mn1);
            ps0 += p0 + p1;
            ps1 += p2 + p3;
            int ks = nf >> 1, base = (nf & 1) << 1;
            aph[ks][base + 0] = pack2bf(p0, p1);
            aph[ks][base + 1] = pack2bf(p2, p3);
        }
        ps0 += __shfl_xor_sync(0xffffffffu, ps0, 1);
        ps0 += __shfl_xor_sync(0xffffffffu, ps0, 2);
        ps1 += __shfl_xor_sync(0xffffffffu, ps1, 1);
        ps1 += __shfl_xor_sync(0xffffffffu, ps1, 2);
        l0 = l0 * al0 + ps0;
        l1 = l1 * al1 + ps1;

        CP_WAIT(1);
        GBAR(gid + 1);
        // ---- O += P·Vh ----
#pragma unroll
        for (int ks = 0; ks < 4; ks++) {
            const int kk = ks << 4;
#pragma unroll
            for (int dg = 0; dg < 2; dg++) {
                uint32_t bvh[4];
                uint32_t offv = (uint32_t)(((kk + a_r) * 40 + (dg << 4) + a_k) << 1);
                ldsm4t(bvh[0], bvh[1], bvh[2], bvh[3], uVh + offv);
#pragma unroll
                for (int sub = 0; sub < 2; sub++) {
                    int nf = (dg << 1) + sub;
                    mma_bf16(of[nf], aph[ks], &bvh[sub << 1]);
                }
            }
        }
    }

    // ---- split-softmax merge ----
    CP_WAIT(0);
    __syncthreads();
    float* mg = (float*)dsm;
    float* lg = mg + 256;
    float* og = lg + 256;
    if (gid == 1) {
        mg[gt * 2] = m0;
        mg[gt * 2 + 1] = m1;
        lg[gt * 2] = l0;
        lg[gt * 2 + 1] = l1;
#pragma unroll
        for (int nf = 0; nf < 4; nf++)
#pragma unroll
            for (int c = 0; c < 4; c++) og[gt * 16 + nf * 4 + c] = of[nf][c];
    }
    __syncthreads();
    if (gid == 0) {
        float mb0 = mg[gt * 2], mb1 = mg[gt * 2 + 1];
        float lb0 = lg[gt * 2], lb1 = lg[gt * 2 + 1];
        float mn0 = fmaxf(m0, mb0), mn1 = fmaxf(m1, mb1);
        float a0 = ex2f(m0 - mn0), bb0 = ex2f(mb0 - mn0);
        float a1 = ex2f(m1 - mn1), bb1 = ex2f(mb1 - mn1);
        float inv0 = 1.0f / (l0 * a0 + lb0 * bb0);
        float inv1 = 1.0f / (l1 * a1 + lb1 * bb1);
        int row0 = i0 + mw + lr, row1 = row0 + 8;
#pragma unroll
        for (int nf = 0; nf < 4; nf++) {
            int col = h * DKk + (nf << 3) + lc;
            float v0 = (of[nf][0] * a0 + og[gt * 16 + nf * 4 + 0] * bb0) * inv0;
            float v1 = (of[nf][1] * a0 + og[gt * 16 + nf * 4 + 1] * bb0) * inv0;
            float v2 = (of[nf][2] * a1 + og[gt * 16 + nf * 4 + 2] * bb1) * inv1;
            float v3 = (of[nf][3] * a1 + og[gt * 16 + nf * 4 + 3] * bb1) * inv1;
            float h0 = __bfloat162float(__float2bfloat16(v0));
            float h1 = __bfloat162float(__float2bfloat16(v1));
            float h2 = __bfloat162float(__float2bfloat16(v2));
            float h3 = __bfloat162float(__float2bfloat16(v3));
            *(uint32_t*)&Oh[(size_t)row0 * Dd + col] = pack2bf(h0, h1);
            *(uint32_t*)&Oh[(size_t)row1 * Dd + col] = pack2bf(h2, h3);
            *(uint32_t*)&Ol[(size_t)row0 * Dd + col] = pack2bf(v0 - h0, v1 - h1);
            *(uint32_t*)&Ol[(size_t)row1 * Dd + col] = pack2bf(v2 - h2, v3 - h3);
        }
    }
}

// ---------------- reduce + bias + residual + LayerNorm (R13 256-thr shuffle) ----------------
template <int S>
__global__ void addln_red_kernel(float* __restrict__ x, const float* __restrict__ part,
                                 const float* __restrict__ bias, const float* __restrict__ g,
                                 const float* __restrict__ b, bf16* __restrict__ xh,
                                 bf16* __restrict__ xl) {
    int i = blockIdx.x, d = threadIdx.x;
    int lane = d & 31, w = d >> 5;
    __shared__ float ws[8];
    float v = x[i * Dd + d] + bias[d];
#pragma unroll
    for (int s = 0; s < S; s++) v += part[(size_t)s * Nn * Dd + (size_t)i * Dd + d];
    float t = v;
#pragma unroll
    for (int off = 16; off > 0; off >>= 1) t += __shfl_xor_sync(0xffffffffu, t, off);
    if (lane == 0) ws[w] = t;
    __syncthreads();
    float mean = (ws[0] + ws[1] + ws[2] + ws[3] + ws[4] + ws[5] + ws[6] + ws[7]) * (1.0f / Dd);
    float dv = v - mean;
    t = dv * dv;
#pragma unroll
    for (int off = 16; off > 0; off >>= 1) t += __shfl_xor_sync(0xffffffffu, t, off);
    __syncthreads();
    if (lane == 0) ws[w] = t;
    __syncthreads();
    float var = (ws[0] + ws[1] + ws[2] + ws[3] + ws[4] + ws[5] + ws[6] + ws[7]) * (1.0f / Dd);
    float outv = dv * rsqrtf(var + 1e-5f) * g[d] + b[d];
    x[i * Dd + d] = outv;
    bf16 h = __float2bfloat16(outv);
    xh[i * Dd + d] = h;
    xl[i * Dd + d] = __float2bfloat16(outv - __bfloat162float(h));
}

__global__ void pool_kernel(const float* __restrict__ x, float* __restrict__ p) {
    int j = blockIdx.x * 32 + threadIdx.x;
    int yy = threadIdx.y;
    float s = 0.f, mx = -1e30f;
    for (int i = yy; i < Nn; i += 8) {
        float v = x[(size_t)i * Dd + j];
        s += v;
        mx = fmaxf(mx, v);
    }
    __shared__ float ss[8][33], sm[8][33];
    ss[yy][threadIdx.x] = s;
    sm[yy][threadIdx.x] = mx;
    __syncthreads();
    if (yy == 0) {
        for (int k2 = 1; k2 < 8; k2++) {
            s += ss[k2][threadIdx.x];
            mx = fmaxf(mx, sm[k2][threadIdx.x]);
        }
        p[j] = s * (1.0f / Nn);
        p[Dd + j] = mx;
    }
}

__global__ void head_kernel(const float* __restrict__ pooled, const float* __restrict__ Wr,
                            const float* __restrict__ br, float* __restrict__ out) {
    __shared__ float sp[2 * Dd];
    int d = threadIdx.x;
    sp[d] = pooled[d];
    sp[d + Dd] = pooled[d + Dd];
    __syncthreads();
    float acc = br[d];
#pragma unroll 8
    for (int k2 = 0; k2 < 2 * Dd; k2++) acc = fmaf(sp[k2], Wr[(size_t)k2 * Dd + d], acc);
    out[d] = acc;
}

// ---------------- host launcher ----------------
extern "C" void kernel_launch(void* const* d_in, const int* in_sizes, int n_in,
                              void* d_out, int out_size) {
    const int* node_types = (const int*)d_in[0];
    const int* edge_idx = (const int*)d_in[1];
    const float* node_emb = (const float*)d_in[2];
    const float* Wq = (const float*)d_in[3];
    const float* Wk = (const float*)d_in[4];
    const float* Wv = (const float*)d_in[5];
    const float* Wo = (const float*)d_in[6];
    const float* bo = (const float*)d_in[7];
    const float* eb = (const float*)d_in[8];
    const float* W1 = (const float*)d_in[9];
    const float* b1 = (const float*)d_in[10];
    const float* W2 = (const float*)d_in[11];
    const float* b2 = (const float*)d_in[12];
    const float* ln1g = (const float*)d_in[13];
    const float* ln1b = (const float*)d_in[14];
    const float* ln2g = (const float*)d_in[15];
    const float* ln2b = (const float*)d_in[16];
    const float* Wr = (const float*)d_in[17];
    const float* brr = (const float*)d_in[18];
    float* out = (float*)d_out;

    float *x, *part, *pool;
    unsigned char* e8;
    bf16 *xh, *xl, *qh, *ql, *kh, *kl, *vh, *vl, *atth, *attl, *t1h, *t1l;
    bf16 *wqh, *wql, *wkh, *wkl, *wvh, *wvl, *woh, *wol, *w1h, *w1l, *w2h, *w2l;
    cudaGetSymbolAddress((void**)&x, g_x);
    cudaGetSymbolAddress((void**)&part, g_part);
    cudaGetSymbolAddress((void**)&pool, g_pool);
    cudaGetSymbolAddress((void**)&e8, g_e8);
    cudaGetSymbolAddress((void**)&xh, g_xh);
    cudaGetSymbolAddress((void**)&xl, g_xl);
    cudaGetSymbolAddress((void**)&qh, g_qh);
    cudaGetSymbolAddress((void**)&ql, g_ql);
    cudaGetSymbolAddress((void**)&kh, g_kh);
    cudaGetSymbolAddress((void**)&kl, g_kl);
    cudaGetSymbolAddress((void**)&vh, g_vh);
    cudaGetSymbolAddress((void**)&vl, g_vl);
    cudaGetSymbolAddress((void**)&atth, g_atth);
    cudaGetSymbolAddress((void**)&attl, g_attl);
    cudaGetSymbolAddress((void**)&t1h, g_t1h);
    cudaGetSymbolAddress((void**)&t1l, g_t1l);
    cudaGetSymbolAddress((void**)&wqh, g_wqh);
    cudaGetSymbolAddress((void**)&wql, g_wql);
    cudaGetSymbolAddress((void**)&wkh, g_wkh);
    cudaGetSymbolAddress((void**)&wkl, g_wkl);
    cudaGetSymbolAddress((void**)&wvh, g_wvh);
    cudaGetSymbolAddress((void**)&wvl, g_wvl);
    cudaGetSymbolAddress((void**)&woh, g_woh);
    cudaGetSymbolAddress((void**)&wol, g_wol);
    cudaGetSymbolAddress((void**)&w1h, g_w1h);
    cudaGetSymbolAddress((void**)&w1l, g_w1l);
    cudaGetSymbolAddress((void**)&w2h, g_w2h);
    cudaGetSymbolAddress((void**)&w2l, g_w2l);

    cudaFuncSetAttribute(attn_hmma_kernel, cudaFuncAttributeMaxDynamicSharedMemorySize,
                         ATTN_SMEM);
    cudaFuncSetAttribute(hmma_qkv_kernel, cudaFuncAttributeMaxDynamicSharedMemorySize,
                         GEMM_SMEM);
    cudaFuncSetAttribute(hmma_gemm_kernel<0, 2, 0>, cudaFuncAttributeMaxDynamicSharedMemorySize,
                         GEMM_SMEM);
    cudaFuncSetAttribute(hmma_gemm_kernel<1, 1, 1>, cudaFuncAttributeMaxDynamicSharedMemorySize,
                         GEMM_SMEM);

    embed_kernel<<<Nn, Dd>>>(node_types, node_emb, x, xh, xl);
    cvt_e8_kernel<<<(Nn * Nn / 4) / 256, 256>>>(edge_idx, e8);

    wsplit4_kernel<<<dim3(8, 8, 4 * Ll), dim3(32, 8)>>>(Wq, Wk, Wv, Wo, wqh, wql, wkh, wkl,
                                                        wvh, wvl, woh, wol);
    wsplit_kernel<<<dim3(32, 8, Ll), dim3(32, 8)>>>(W1, w1h, w1l, Dd, DFFf);
    wsplit_kernel<<<dim3(8, 32, Ll), dim3(32, 8)>>>(W2, w2h, w2l, DFFf, Dd);

    for (int l = 0; l < Ll; l++) {
        size_t wo256 = (size_t)l * Dd * Dd;
        size_t woff1 = (size_t)l * Dd * DFFf;
        hmma_qkv_kernel<<<dim3(4, 16, 3), 256, GEMM_SMEM>>>(
            xh, xl, wqh + wo256, wql + wo256, wkh + wo256, wkl + wo256, wvh + wo256,
            wvl + wo256, qh, kh, kl, vh, vl);

        attn_hmma_kernel<<<dim3(Nn / 64, Hh), 256, ATTN_SMEM>>>(
            qh, kh, kl, vh, e8, eb + l * NEDGEe * Hh, atth, attl);

        hmma_gemm_kernel<0, 2, 0><<<dim3(4, 16, 2), 256, GEMM_SMEM>>>(
            atth, attl, woh + wo256, wol + wo256, nullptr, part, nullptr, nullptr, Dd, Dd);
        addln_red_kernel<2><<<Nn, Dd>>>(x, part, bo + l * Dd, ln1g + l * Dd, ln1b + l * Dd, xh,
                                        xl);

        hmma_gemm_kernel<1, 1, 1><<<dim3(16, 16, 1), 256, GEMM_SMEM>>>(
            xh, xl, w1h + woff1, w1l + woff1, b1 + l * DFFf, nullptr, t1h, t1l, Dd, DFFf);

        hmma_gemm_kernel<0, 2, 0><<<dim3(4, 16, 2), 256, GEMM_SMEM>>>(
            t1h, t1l, w2h + woff1, w2l + woff1, nullptr, part, nullptr, nullptr, DFFf, Dd);
        addln_red_kernel<2><<<Nn, Dd>>>(x, part, b2 + l * Dd, ln2g + l * Dd, ln2b + l * Dd, xh,
                                        xl);
    }

    pool_kernel<<<Dd / 32, dim3(32, 8)>>>(x, pool);
    head_kernel<<<1, Dd>>>(pool, Wr, brr, out);
}